// round 2
// baseline (speedup 1.0000x reference)
#include <cuda_runtime.h>
#include <math.h>

#define N_ 100000
#define E_ 500000
#define D_ 128
#define T_ 3
#define R_ 4
#define H_ 8
#define ML_ 240
#define TD_ ((size_t)N_*(size_t)D_)

__device__ float g_x[TD_];
__device__ float g_Qn[TD_];
__device__ float g_Kn[TD_];
__device__ float g_Vn[TD_];
__device__ float g_aggr[TD_];
__device__ float g_score[(size_t)E_*H_];
__device__ int   g_mx[N_*H_];
__device__ float g_den[N_*H_];
__device__ float g_rte_tab[ML_*2*D_];
__device__ float g_rte_proj[ML_*D_];
__device__ float g_tabK[T_*ML_*D_];
__device__ float g_tabV[T_*ML_*D_];
__device__ int   g_typeList[T_][N_];
__device__ int   g_typeCnt[T_];
__device__ int   g_rCnt[R_];
__device__ int   g_rOff[R_+1];
__device__ int   g_rFill[R_];
__device__ int   g_eS[E_];
__device__ int   g_eT[E_];
__device__ int   g_eMeta[E_];   // st | tt<<2 | time<<4
__device__ int   g_eId[E_];

__device__ __forceinline__ int fmap(float f) {
    int i = __float_as_int(f);
    return i >= 0 ? i : (i ^ 0x7fffffff);
}
__device__ __forceinline__ float funmap(int i) {
    return __int_as_float(i >= 0 ? i : (i ^ 0x7fffffff));
}
__device__ __forceinline__ float gelu_f(float x) { return x * normcdff(x); }

__device__ __forceinline__ void red_add_v4(float* p, float a, float b, float c, float d) {
    asm volatile("red.global.add.v4.f32 [%0], {%1,%2,%3,%4};"
                 :: "l"(p), "f"(a), "f"(b), "f"(c), "f"(d) : "memory");
}

__global__ void k_rte_tab() {
    int pos = blockIdx.x;      // 0..239
    int i   = threadIdx.x;     // 0..127
    const float s = 0.08838834764831845f;  // 1/sqrt(128)
    float div;
    if (i >= 5) {
        div = 0.f;             // fp32 10000^ar overflows to inf -> div = 0
    } else {
        float pf = (float)pow(10000.0, (double)(2 * i));
        div = 1.0f / ((pf / 128.0f) / 2.0f);
    }
    float ang = (float)pos * div;
    double a = (double)ang;
    g_rte_tab[pos * 256 + 2 * i]     = (float)sin(a) * s;
    g_rte_tab[pos * 256 + 2 * i + 1] = (float)cos(a) * s;
}

__global__ void k_rte_proj(const float* __restrict__ w, const float* __restrict__ b) {
    int time = blockIdx.x;   // 0..239
    int d    = threadIdx.x;  // 0..127
    float acc = b[d];
    const float* tr = g_rte_tab + time * 256;
    for (int c = 0; c < 256; c++) acc += tr[c] * w[c * 128 + d];
    g_rte_proj[time * 128 + d] = acc;
}

__global__ void k_tables(const float* __restrict__ Wk, const float* __restrict__ Wv) {
    int id = blockIdx.x;          // 0..T*240-1
    int d  = threadIdx.x;         // 0..127
    int t = id / ML_, time = id % ML_;
    const float* pr = g_rte_proj + time * 128;
    const float* wk = Wk + (size_t)t * 128 * 128;
    const float* wv = Wv + (size_t)t * 128 * 128;
    float aK = 0.f, aV = 0.f;
    for (int k = 0; k < 128; k++) {
        float p = pr[k];
        aK += p * wk[k * 128 + d];
        aV += p * wv[k * 128 + d];
    }
    g_tabK[(t * ML_ + time) * 128 + d] = aK;
    g_tabV[(t * ML_ + time) * 128 + d] = aV;
}

__global__ void k_init_once() {
    int i = threadIdx.x;
    if (i < T_) g_typeCnt[i] = 0;
    if (i < R_) { g_rCnt[i] = 0; g_rFill[i] = 0; }
}

__global__ void k_build_type(const int* __restrict__ nt) {
    int i = blockIdx.x * blockDim.x + threadIdx.x;
    if (i < N_) {
        int t = nt[i];
        int p = atomicAdd(&g_typeCnt[t], 1);
        g_typeList[t][p] = i;
    }
}

__global__ void k_count_r(const int* __restrict__ et) {
    int i = blockIdx.x * blockDim.x + threadIdx.x;
    if (i < E_) atomicAdd(&g_rCnt[et[i]], 1);
}

__global__ void k_scan_r() {
    g_rOff[0] = 0;
    for (int r = 0; r < R_; r++) g_rOff[r + 1] = g_rOff[r] + g_rCnt[r];
}

__global__ void k_scatter_r(const int* __restrict__ src, const int* __restrict__ tgt,
                            const int* __restrict__ et, const int* __restrict__ etm,
                            const int* __restrict__ nt) {
    int e = blockIdx.x * blockDim.x + threadIdx.x;
    if (e < E_) {
        int r = et[e];
        int p = g_rOff[r] + atomicAdd(&g_rFill[r], 1);
        int s = src[e], t = tgt[e];
        g_eS[p] = s;
        g_eT[p] = t;
        g_eId[p] = e;
        g_eMeta[p] = nt[s] | (nt[t] << 2) | (etm[e] << 4);
    }
}

__global__ void k_init_layer() {
    int stride = gridDim.x * blockDim.x;
    int i0 = blockIdx.x * blockDim.x + threadIdx.x;
    for (int i = i0; i < N_ * H_; i += stride) { g_mx[i] = 0x807FFFFF; g_den[i] = 0.f; }
    for (size_t i = i0; i < TD_; i += (size_t)stride) g_aggr[i] = 0.f;
}

// typed GEMM: out[row] = epilogue( op(in[row]) @ W[type] + b[type] )
// inop: 0=none, 1=gelu. outop: 0=bias only, 1=tanh, 2=skip-mix
__global__ void __launch_bounds__(256) k_typed_gemm(
    int inop, int outop,
    const float* __restrict__ in,
    const float* __restrict__ Wbase,
    const float* __restrict__ Bbase,
    float* __restrict__ out,
    const float* __restrict__ skipv)
{
    int t = blockIdx.y;
    int cnt = g_typeCnt[t];
    int base = blockIdx.x * 128;
    if (base >= cnt) return;
    const int* list = &g_typeList[t][base];
    int rem = cnt - base; if (rem > 128) rem = 128;

    __shared__ float As[16][128];
    __shared__ float Ws[16][128];

    int tid = threadIdx.x;
    int lr = tid >> 1;
    int lq = (tid & 1) * 8;
    int lrow = (lr < rem) ? list[lr] : list[0];
    const float* arow = in + (size_t)lrow * D_ + lq;

    int wk = tid >> 4;
    int wc = (tid & 15) * 8;
    const float* Wt = Wbase + (size_t)t * 128 * 128;

    int ty = tid >> 4, tx = tid & 15;
    int row0 = ty * 8, col0 = tx * 8;
    float acc[8][8];
    #pragma unroll
    for (int i = 0; i < 8; i++)
        #pragma unroll
        for (int j = 0; j < 8; j++) acc[i][j] = 0.f;

    for (int k0 = 0; k0 < 128; k0 += 16) {
        float4 a0 = *(const float4*)(arow + k0);
        float4 a1 = *(const float4*)(arow + k0 + 4);
        float4 w0 = *(const float4*)(Wt + (k0 + wk) * 128 + wc);
        float4 w1 = *(const float4*)(Wt + (k0 + wk) * 128 + wc + 4);
        if (inop == 1) {
            a0.x = gelu_f(a0.x); a0.y = gelu_f(a0.y); a0.z = gelu_f(a0.z); a0.w = gelu_f(a0.w);
            a1.x = gelu_f(a1.x); a1.y = gelu_f(a1.y); a1.z = gelu_f(a1.z); a1.w = gelu_f(a1.w);
        }
        __syncthreads();
        As[lq + 0][lr] = a0.x; As[lq + 1][lr] = a0.y; As[lq + 2][lr] = a0.z; As[lq + 3][lr] = a0.w;
        As[lq + 4][lr] = a1.x; As[lq + 5][lr] = a1.y; As[lq + 6][lr] = a1.z; As[lq + 7][lr] = a1.w;
        *(float4*)(&Ws[wk][wc]) = w0;
        *(float4*)(&Ws[wk][wc + 4]) = w1;
        __syncthreads();
        #pragma unroll
        for (int kk = 0; kk < 16; kk++) {
            float4 aa0 = *(const float4*)(&As[kk][row0]);
            float4 aa1 = *(const float4*)(&As[kk][row0 + 4]);
            float4 ww0 = *(const float4*)(&Ws[kk][col0]);
            float4 ww1 = *(const float4*)(&Ws[kk][col0 + 4]);
            float av[8] = {aa0.x, aa0.y, aa0.z, aa0.w, aa1.x, aa1.y, aa1.z, aa1.w};
            float wv[8] = {ww0.x, ww0.y, ww0.z, ww0.w, ww1.x, ww1.y, ww1.z, ww1.w};
            #pragma unroll
            for (int i = 0; i < 8; i++)
                #pragma unroll
                for (int j = 0; j < 8; j++)
                    acc[i][j] += av[i] * wv[j];
        }
    }

    const float* Bt = Bbase + t * D_;
    float4 b0 = *(const float4*)(Bt + col0);
    float4 b1 = *(const float4*)(Bt + col0 + 4);
    float bv[8] = {b0.x, b0.y, b0.z, b0.w, b1.x, b1.y, b1.z, b1.w};
    float alpha = 0.f;
    if (outop == 2) alpha = 1.f / (1.f + expf(-skipv[t]));

    #pragma unroll
    for (int i = 0; i < 8; i++) {
        int rr = row0 + i;
        if (rr < rem) {
            int grow = list[rr];
            float* op = out + (size_t)grow * D_ + col0;
            float res[8];
            #pragma unroll
            for (int j = 0; j < 8; j++) {
                float v = acc[i][j] + bv[j];
                if (outop == 1) v = tanhf(v);
                else if (outop == 2) v = alpha * v + (1.f - alpha) * op[j];
                res[j] = v;
            }
            *(float4*)op       = make_float4(res[0], res[1], res[2], res[3]);
            *(float4*)(op + 4) = make_float4(res[4], res[5], res[6], res[7]);
        }
    }
}

// edge pass A: per-edge-head score = q . (rel_att^T k), + segment max
__global__ void __launch_bounds__(256) k_edgeA(const float* __restrict__ relAtt,
                                               const float* __restrict__ relPri) {
    int r = blockIdx.y;
    __shared__ float sA[H_ * 260];
    const float* Ar = relAtt + r * H_ * 256;
    for (int i = threadIdx.x; i < H_ * 256; i += blockDim.x)
        sA[(i >> 8) * 260 + (i & 255)] = Ar[i];
    __syncthreads();

    int lo = g_rOff[r], hi = g_rOff[r + 1];
    int lane = threadIdx.x & 31;
    int h = lane & 7, esub = lane >> 3;
    int warp = blockIdx.x * (blockDim.x >> 5) + (threadIdx.x >> 5);
    int nwarp = gridDim.x * (blockDim.x >> 5);
    const float* A = sA + h * 260;

    for (int eb = lo + warp * 4; eb < hi; eb += nwarp * 4) {
        int p = eb + esub;
        bool valid = p < hi;
        if (!valid) p = lo;
        int s = g_eS[p], t = g_eT[p], meta = g_eMeta[p], e = g_eId[p];
        int st = meta & 3, tt = (meta >> 2) & 3, tm = meta >> 4;

        const float* kp = g_Kn + (size_t)s * D_ + h * 16;
        const float* tp = g_tabK + (size_t)(st * ML_ + tm) * 128 + h * 16;
        float kr[16];
        #pragma unroll
        for (int q4 = 0; q4 < 4; q4++) {
            float4 a = *(const float4*)(kp + q4 * 4);
            float4 b = *(const float4*)(tp + q4 * 4);
            kr[q4 * 4 + 0] = a.x + b.x; kr[q4 * 4 + 1] = a.y + b.y;
            kr[q4 * 4 + 2] = a.z + b.z; kr[q4 * 4 + 3] = a.w + b.w;
        }
        float acc[16];
        #pragma unroll
        for (int j = 0; j < 16; j++) acc[j] = 0.f;
        #pragma unroll
        for (int kk = 0; kk < 16; kk++) {
            float kv = kr[kk];
            const float4* ap = (const float4*)(A + kk * 16);
            float4 a0 = ap[0], a1 = ap[1], a2 = ap[2], a3 = ap[3];
            acc[0]  += kv * a0.x; acc[1]  += kv * a0.y; acc[2]  += kv * a0.z; acc[3]  += kv * a0.w;
            acc[4]  += kv * a1.x; acc[5]  += kv * a1.y; acc[6]  += kv * a1.z; acc[7]  += kv * a1.w;
            acc[8]  += kv * a2.x; acc[9]  += kv * a2.y; acc[10] += kv * a2.z; acc[11] += kv * a2.w;
            acc[12] += kv * a3.x; acc[13] += kv * a3.y; acc[14] += kv * a3.z; acc[15] += kv * a3.w;
        }
        const float4* qp = (const float4*)(g_Qn + (size_t)t * D_ + h * 16);
        float4 q0 = qp[0], q1 = qp[1], q2 = qp[2], q3 = qp[3];
        float sc = q0.x * acc[0]  + q0.y * acc[1]  + q0.z * acc[2]  + q0.w * acc[3]
                 + q1.x * acc[4]  + q1.y * acc[5]  + q1.z * acc[6]  + q1.w * acc[7]
                 + q2.x * acc[8]  + q2.y * acc[9]  + q2.z * acc[10] + q2.w * acc[11]
                 + q3.x * acc[12] + q3.y * acc[13] + q3.z * acc[14] + q3.w * acc[15];
        float pri = relPri[((tt * R_ + r) * T_ + st) * H_ + h];
        sc *= pri * 0.25f;
        if (valid) {
            g_score[(size_t)e * H_ + h] = sc;
            atomicMax(&g_mx[t * H_ + h], fmap(sc));
        }
    }
}

__global__ void k_edgeB(const int* __restrict__ tgt) {
    int idx = blockIdx.x * blockDim.x + threadIdx.x;
    if (idx >= E_ * H_) return;
    int e = idx >> 3, h = idx & 7;
    int t = tgt[e];
    float m = funmap(g_mx[t * H_ + h]);
    float ex = expf(g_score[idx] - m);
    g_score[idx] = ex;
    atomicAdd(&g_den[t * H_ + h], ex);
}

__global__ void __launch_bounds__(256) k_edgeC(const float* __restrict__ relMsg) {
    int r = blockIdx.y;
    __shared__ float sA[H_ * 260];
    const float* Ar = relMsg + r * H_ * 256;
    for (int i = threadIdx.x; i < H_ * 256; i += blockDim.x)
        sA[(i >> 8) * 260 + (i & 255)] = Ar[i];
    __syncthreads();

    int lo = g_rOff[r], hi = g_rOff[r + 1];
    int lane = threadIdx.x & 31;
    int h = lane & 7, esub = lane >> 3;
    int warp = blockIdx.x * (blockDim.x >> 5) + (threadIdx.x >> 5);
    int nwarp = gridDim.x * (blockDim.x >> 5);
    const float* A = sA + h * 260;

    for (int eb = lo + warp * 4; eb < hi; eb += nwarp * 4) {
        int p = eb + esub;
        bool valid = p < hi;
        if (!valid) p = lo;
        int s = g_eS[p], t = g_eT[p], meta = g_eMeta[p], e = g_eId[p];
        int st = meta & 3, tm = meta >> 4;

        const float* vp = g_Vn + (size_t)s * D_ + h * 16;
        const float* tp = g_tabV + (size_t)(st * ML_ + tm) * 128 + h * 16;
        float vr[16];
        #pragma unroll
        for (int q4 = 0; q4 < 4; q4++) {
            float4 a = *(const float4*)(vp + q4 * 4);
            float4 b = *(const float4*)(tp + q4 * 4);
            vr[q4 * 4 + 0] = a.x + b.x; vr[q4 * 4 + 1] = a.y + b.y;
            vr[q4 * 4 + 2] = a.z + b.z; vr[q4 * 4 + 3] = a.w + b.w;
        }
        float acc[16];
        #pragma unroll
        for (int j = 0; j < 16; j++) acc[j] = 0.f;
        #pragma unroll
        for (int kk = 0; kk < 16; kk++) {
            float kv = vr[kk];
            const float4* ap = (const float4*)(A + kk * 16);
            float4 a0 = ap[0], a1 = ap[1], a2 = ap[2], a3 = ap[3];
            acc[0]  += kv * a0.x; acc[1]  += kv * a0.y; acc[2]  += kv * a0.z; acc[3]  += kv * a0.w;
            acc[4]  += kv * a1.x; acc[5]  += kv * a1.y; acc[6]  += kv * a1.z; acc[7]  += kv * a1.w;
            acc[8]  += kv * a2.x; acc[9]  += kv * a2.y; acc[10] += kv * a2.z; acc[11] += kv * a2.w;
            acc[12] += kv * a3.x; acc[13] += kv * a3.y; acc[14] += kv * a3.z; acc[15] += kv * a3.w;
        }
        float ex = g_score[(size_t)e * H_ + h];
        float den = g_den[t * H_ + h];
        float att = ex / den;
        if (valid) {
            float* op = g_aggr + (size_t)t * D_ + h * 16;
            red_add_v4(op,      acc[0] * att,  acc[1] * att,  acc[2] * att,  acc[3] * att);
            red_add_v4(op + 4,  acc[4] * att,  acc[5] * att,  acc[6] * att,  acc[7] * att);
            red_add_v4(op + 8,  acc[8] * att,  acc[9] * att,  acc[10] * att, acc[11] * att);
            red_add_v4(op + 12, acc[12] * att, acc[13] * att, acc[14] * att, acc[15] * att);
        }
    }
}

__global__ void k_out(float* __restrict__ o) {
    int i = blockIdx.x * blockDim.x + threadIdx.x;
    int n4 = (int)(TD_ / 4);
    if (i < n4) ((float4*)o)[i] = ((const float4*)g_x)[i];
}

extern "C" void kernel_launch(void* const* d_in, const int* in_sizes, int n_in,
                              void* d_out, int out_size) {
    const float* node_feature = (const float*)d_in[0];
    const int*   node_type    = (const int*)d_in[1];
    const int*   edge_index   = (const int*)d_in[2];
    const int*   edge_type    = (const int*)d_in[3];
    const int*   edge_time    = (const int*)d_in[4];
    const float* adapt_w      = (const float*)d_in[5];
    const float* adapt_b      = (const float*)d_in[6];
    const float* Wk           = (const float*)d_in[7];
    const float* bk           = (const float*)d_in[8];
    const float* Wq           = (const float*)d_in[9];
    const float* bq           = (const float*)d_in[10];
    const float* Wv           = (const float*)d_in[11];
    const float* bv           = (const float*)d_in[12];
    const float* Wa           = (const float*)d_in[13];
    const float* ba           = (const float*)d_in[14];
    const float* rel_pri      = (const float*)d_in[15];
    const float* rel_att      = (const float*)d_in[16];
    const float* rel_msg      = (const float*)d_in[17];
    const float* skip         = (const float*)d_in[18];
    const float* rte_w        = (const float*)d_in[19];
    const float* rte_b        = (const float*)d_in[20];

    const int* src = edge_index;
    const int* tgt = edge_index + E_;

    float *px, *pq, *pk, *pv, *pa;
    cudaGetSymbolAddress((void**)&px, g_x);
    cudaGetSymbolAddress((void**)&pq, g_Qn);
    cudaGetSymbolAddress((void**)&pk, g_Kn);
    cudaGetSymbolAddress((void**)&pv, g_Vn);
    cudaGetSymbolAddress((void**)&pa, g_aggr);

    k_rte_tab<<<ML_, 128>>>();
    k_init_once<<<1, 32>>>();
    k_build_type<<<(N_ + 255) / 256, 256>>>(node_type);
    k_count_r<<<(E_ + 255) / 256, 256>>>(edge_type);
    k_scan_r<<<1, 1>>>();
    k_scatter_r<<<(E_ + 255) / 256, 256>>>(src, tgt, edge_type, edge_time, node_type);

    dim3 ggrid((N_ + 127) / 128, T_);
    dim3 egrid(128, R_);

    // x = tanh(typed_linear(node_feature; adapt))
    k_typed_gemm<<<ggrid, 256>>>(0, 1, node_feature, adapt_w, adapt_b, px, nullptr);

    for (int l = 0; l < 2; l++) {
        size_t woff = (size_t)l * T_ * 128 * 128;
        size_t boff = (size_t)l * T_ * 128;
        k_rte_proj<<<ML_, 128>>>(rte_w + (size_t)l * 256 * 128, rte_b + (size_t)l * 128);
        k_tables<<<T_ * ML_, 128>>>(Wk + woff, Wv + woff);

        k_typed_gemm<<<ggrid, 256>>>(0, 0, px, Wq + woff, bq + boff, pq, nullptr);
        k_typed_gemm<<<ggrid, 256>>>(0, 0, px, Wk + woff, bk + boff, pk, nullptr);
        k_typed_gemm<<<ggrid, 256>>>(0, 0, px, Wv + woff, bv + boff, pv, nullptr);

        k_init_layer<<<2048, 256>>>();
        k_edgeA<<<egrid, 256>>>(rel_att + (size_t)l * R_ * H_ * 256,
                                rel_pri + (size_t)l * T_ * R_ * T_ * H_);
        k_edgeB<<<(E_ * H_ + 255) / 256, 256>>>(tgt);
        k_edgeC<<<egrid, 256>>>(rel_msg + (size_t)l * R_ * H_ * 256);

        // x = alpha * typed_linear(gelu(aggr); Wa) + (1-alpha) * x
        k_typed_gemm<<<ggrid, 256>>>(1, 2, pa, Wa + woff, ba + boff, px, skip + (size_t)l * T_);
    }

    k_out<<<(int)((TD_ / 4 + 255) / 256), 256>>>((float*)d_out);
}

// round 3
// speedup vs baseline: 1.1024x; 1.1024x over previous
#include <cuda_runtime.h>
#include <cuda_bf16.h>
#include <math.h>

#define N_ 100000
#define E_ 500000
#define D_ 128
#define T_ 3
#define R_ 4
#define H_ 8
#define ML_ 240
#define TD_ ((size_t)N_*(size_t)D_)
#define PAD_ 136                      // bf16 elems per smem row (272B stride)
#define GEMM_SMEM (4 * 128 * PAD_ * 2)  // Ahi, Alo, Whi, Wlo

__device__ float g_x[TD_];
__device__ float g_Qn[TD_];
__device__ float g_Kn[TD_];
__device__ float g_Vn[TD_];
__device__ float g_aggr[TD_];
__device__ float g_score[(size_t)E_*H_];
__device__ int   g_mx[N_*H_];
__device__ float g_den[N_*H_];
__device__ float g_rte_tab[ML_*2*D_];
__device__ float g_rte_proj[ML_*D_];
__device__ float g_tabK[T_*ML_*D_];
__device__ float g_tabV[T_*ML_*D_];
__device__ int   g_typeList[T_][N_];
__device__ int   g_typeCnt[T_];
__device__ int   g_rCnt[R_];
__device__ int   g_rOff[R_+1];
__device__ int   g_rFill[R_];
__device__ int   g_eS[E_];
__device__ int   g_eT[E_];
__device__ int   g_eMeta[E_];   // st | tt<<2 | time<<4
__device__ int   g_eId[E_];

__device__ __forceinline__ int fmap(float f) {
    int i = __float_as_int(f);
    return i >= 0 ? i : (i ^ 0x7fffffff);
}
__device__ __forceinline__ float funmap(int i) {
    return __int_as_float(i >= 0 ? i : (i ^ 0x7fffffff));
}
__device__ __forceinline__ float gelu_f(float x) { return x * normcdff(x); }

__device__ __forceinline__ void red_add_v4(float* p, float a, float b, float c, float d) {
    asm volatile("red.global.add.v4.f32 [%0], {%1,%2,%3,%4};"
                 :: "l"(p), "f"(a), "f"(b), "f"(c), "f"(d) : "memory");
}

// ---------------- mma helpers ----------------
__device__ __forceinline__ void ldsm4(unsigned& r0, unsigned& r1, unsigned& r2, unsigned& r3,
                                      unsigned addr) {
    asm volatile("ldmatrix.sync.aligned.m8n8.x4.shared.b16 {%0,%1,%2,%3}, [%4];"
                 : "=r"(r0), "=r"(r1), "=r"(r2), "=r"(r3) : "r"(addr));
}
__device__ __forceinline__ void ldsm4t(unsigned& r0, unsigned& r1, unsigned& r2, unsigned& r3,
                                       unsigned addr) {
    asm volatile("ldmatrix.sync.aligned.m8n8.x4.trans.shared.b16 {%0,%1,%2,%3}, [%4];"
                 : "=r"(r0), "=r"(r1), "=r"(r2), "=r"(r3) : "r"(addr));
}
__device__ __forceinline__ void mma16816(float* d, const unsigned* a, const unsigned* b) {
    asm volatile("mma.sync.aligned.m16n8k16.row.col.f32.bf16.bf16.f32 "
                 "{%0,%1,%2,%3}, {%4,%5,%6,%7}, {%8,%9}, {%0,%1,%2,%3};"
                 : "+f"(d[0]), "+f"(d[1]), "+f"(d[2]), "+f"(d[3])
                 : "r"(a[0]), "r"(a[1]), "r"(a[2]), "r"(a[3]), "r"(b[0]), "r"(b[1]));
}
__device__ __forceinline__ unsigned pack_bf2(__nv_bfloat16 a, __nv_bfloat16 b) {
    __nv_bfloat162 p(a, b);
    return *reinterpret_cast<unsigned*>(&p);
}

// ---------------- precompute kernels ----------------
__global__ void k_rte_tab() {
    int pos = blockIdx.x;
    int i   = threadIdx.x;
    const float s = 0.08838834764831845f;
    float div;
    if (i >= 5) div = 0.f;   // fp32 10000^ar overflow -> inf -> 0
    else {
        float pf = (float)pow(10000.0, (double)(2 * i));
        div = 1.0f / ((pf / 128.0f) / 2.0f);
    }
    float ang = (float)pos * div;
    double a = (double)ang;
    g_rte_tab[pos * 256 + 2 * i]     = (float)sin(a) * s;
    g_rte_tab[pos * 256 + 2 * i + 1] = (float)cos(a) * s;
}

__global__ void k_rte_proj(const float* __restrict__ w, const float* __restrict__ b) {
    int time = blockIdx.x;
    int d    = threadIdx.x;
    float acc = b[d];
    const float* tr = g_rte_tab + time * 256;
    for (int c = 0; c < 256; c++) acc += tr[c] * w[c * 128 + d];
    g_rte_proj[time * 128 + d] = acc;
}

__global__ void k_tables(const float* __restrict__ Wk, const float* __restrict__ Wv) {
    int id = blockIdx.x;
    int d  = threadIdx.x;
    int t = id / ML_, time = id % ML_;
    const float* pr = g_rte_proj + time * 128;
    const float* wk = Wk + (size_t)t * 128 * 128;
    const float* wv = Wv + (size_t)t * 128 * 128;
    float aK = 0.f, aV = 0.f;
    for (int k = 0; k < 128; k++) {
        float p = pr[k];
        aK += p * wk[k * 128 + d];
        aV += p * wv[k * 128 + d];
    }
    g_tabK[(t * ML_ + time) * 128 + d] = aK;
    g_tabV[(t * ML_ + time) * 128 + d] = aV;
}

// ---------------- bucketing (block-aggregated atomics) ----------------
__global__ void k_init_once() {
    int i = threadIdx.x;
    if (i < T_) g_typeCnt[i] = 0;
    if (i < R_) { g_rCnt[i] = 0; g_rFill[i] = 0; }
}

__global__ void k_build_type(const int* __restrict__ nt) {
    __shared__ int c[T_];
    __shared__ int base[T_];
    int tid = threadIdx.x;
    if (tid < T_) c[tid] = 0;
    __syncthreads();
    int i = blockIdx.x * blockDim.x + tid;
    int t = -1, rank = 0;
    if (i < N_) { t = nt[i]; rank = atomicAdd(&c[t], 1); }
    __syncthreads();
    if (tid < T_) base[tid] = c[tid] ? atomicAdd(&g_typeCnt[tid], c[tid]) : 0;
    __syncthreads();
    if (i < N_) g_typeList[t][base[t] + rank] = i;
}

__global__ void k_count_r(const int* __restrict__ et) {
    __shared__ int c[R_];
    int tid = threadIdx.x;
    if (tid < R_) c[tid] = 0;
    __syncthreads();
    int i = blockIdx.x * blockDim.x + tid;
    if (i < E_) atomicAdd(&c[et[i]], 1);
    __syncthreads();
    if (tid < R_ && c[tid]) atomicAdd(&g_rCnt[tid], c[tid]);
}

__global__ void k_scan_r() {
    g_rOff[0] = 0;
    for (int r = 0; r < R_; r++) g_rOff[r + 1] = g_rOff[r] + g_rCnt[r];
}

__global__ void k_scatter_r(const int* __restrict__ src, const int* __restrict__ tgt,
                            const int* __restrict__ et, const int* __restrict__ etm,
                            const int* __restrict__ nt) {
    __shared__ int c[R_];
    __shared__ int base[R_];
    int tid = threadIdx.x;
    if (tid < R_) c[tid] = 0;
    __syncthreads();
    int e = blockIdx.x * blockDim.x + tid;
    int r = -1, rank = 0;
    if (e < E_) { r = et[e]; rank = atomicAdd(&c[r], 1); }
    __syncthreads();
    if (tid < R_) base[tid] = c[tid] ? atomicAdd(&g_rFill[tid], c[tid]) : 0;
    __syncthreads();
    if (e < E_) {
        int p = g_rOff[r] + base[r] + rank;
        int s = src[e], t = tgt[e];
        g_eS[p] = s;
        g_eT[p] = t;
        g_eId[p] = e;
        g_eMeta[p] = nt[s] | (nt[t] << 2) | (etm[e] << 4);
    }
}

__global__ void k_init_layer() {
    int stride = gridDim.x * blockDim.x;
    int i0 = blockIdx.x * blockDim.x + threadIdx.x;
    for (int i = i0; i < N_ * H_; i += stride) { g_mx[i] = 0x807FFFFF; g_den[i] = 0.f; }
    for (size_t i = i0; i < TD_; i += (size_t)stride) g_aggr[i] = 0.f;
}

// ---------------- tensor-core typed GEMM ----------------
// out[row] = epilogue( op(in[row]) @ W[type] + b[type] )
// inop: 0=none, 1=gelu. outop: 0=bias, 1=tanh, 2=skip-mix
// bf16 3-term split: A=Ah+Al, W=Wh+Wl; acc = Ah*Wh + Al*Wh + Ah*Wl (rel err ~1e-5)
__global__ void __launch_bounds__(256) k_typed_gemm(
    int inop, int outop,
    const float* __restrict__ in,
    const float* __restrict__ Wbase,
    const float* __restrict__ Bbase,
    float* __restrict__ out,
    const float* __restrict__ skipv)
{
    int t = blockIdx.y;
    int cnt = g_typeCnt[t];
    int base = blockIdx.x * 128;
    if (base >= cnt) return;
    const int* list = &g_typeList[t][base];
    int rem = cnt - base; if (rem > 128) rem = 128;

    extern __shared__ __nv_bfloat16 sm[];
    __nv_bfloat16* sAh = sm;
    __nv_bfloat16* sAl = sAh + 128 * PAD_;
    __nv_bfloat16* sWh = sAl + 128 * PAD_;
    __nv_bfloat16* sWl = sWh + 128 * PAD_;
    __shared__ int sList[128];

    int tid = threadIdx.x;
    if (tid < 128) sList[tid] = (tid < rem) ? list[tid] : list[0];
    __syncthreads();

    const float* Wt = Wbase + (size_t)t * 128 * 128;

    // load + convert A (gathered) and W
    #pragma unroll
    for (int it = 0; it < 16; it++) {
        int idx = it * 256 + tid;             // float4 index, 0..4095
        int row = idx >> 5;
        int col = (idx & 31) << 2;
        // A
        {
            int grow = sList[row];
            float4 v = *(const float4*)(in + (size_t)grow * D_ + col);
            if (inop == 1) {
                v.x = gelu_f(v.x); v.y = gelu_f(v.y); v.z = gelu_f(v.z); v.w = gelu_f(v.w);
            }
            __nv_bfloat16 h0 = __float2bfloat16_rn(v.x), h1 = __float2bfloat16_rn(v.y);
            __nv_bfloat16 h2 = __float2bfloat16_rn(v.z), h3 = __float2bfloat16_rn(v.w);
            __nv_bfloat16 l0 = __float2bfloat16_rn(v.x - __bfloat162float(h0));
            __nv_bfloat16 l1 = __float2bfloat16_rn(v.y - __bfloat162float(h1));
            __nv_bfloat16 l2 = __float2bfloat16_rn(v.z - __bfloat162float(h2));
            __nv_bfloat16 l3 = __float2bfloat16_rn(v.w - __bfloat162float(h3));
            uint2 uh = make_uint2(pack_bf2(h0, h1), pack_bf2(h2, h3));
            uint2 ul = make_uint2(pack_bf2(l0, l1), pack_bf2(l2, l3));
            *(uint2*)(sAh + row * PAD_ + col) = uh;
            *(uint2*)(sAl + row * PAD_ + col) = ul;
        }
        // W
        {
            float4 v = *(const float4*)(Wt + row * 128 + col);
            __nv_bfloat16 h0 = __float2bfloat16_rn(v.x), h1 = __float2bfloat16_rn(v.y);
            __nv_bfloat16 h2 = __float2bfloat16_rn(v.z), h3 = __float2bfloat16_rn(v.w);
            __nv_bfloat16 l0 = __float2bfloat16_rn(v.x - __bfloat162float(h0));
            __nv_bfloat16 l1 = __float2bfloat16_rn(v.y - __bfloat162float(h1));
            __nv_bfloat16 l2 = __float2bfloat16_rn(v.z - __bfloat162float(h2));
            __nv_bfloat16 l3 = __float2bfloat16_rn(v.w - __bfloat162float(h3));
            uint2 uh = make_uint2(pack_bf2(h0, h1), pack_bf2(h2, h3));
            uint2 ul = make_uint2(pack_bf2(l0, l1), pack_bf2(l2, l3));
            *(uint2*)(sWh + row * PAD_ + col) = uh;
            *(uint2*)(sWl + row * PAD_ + col) = ul;
        }
    }
    __syncthreads();

    int warp = tid >> 5, lane = tid & 31;
    int wm = warp & 3;       // 4 m-tiles of 32 rows
    int wn = warp >> 2;      // 2 n-tiles of 64 cols
    int mbase = wm * 32;
    int nbase = wn * 64;

    float acc[2][8][4];
    #pragma unroll
    for (int i = 0; i < 2; i++)
        #pragma unroll
        for (int j = 0; j < 8; j++)
            #pragma unroll
            for (int q = 0; q < 4; q++) acc[i][j][q] = 0.f;

    // address lanes
    int aRow = mbase + (lane & 15);
    int aColAdd = (lane >> 4) << 3;
    int bg = lane >> 3;
    int bRowAdd = ((bg & 1) << 3) + (lane & 7);
    int bColAdd = (bg >> 1) << 3;

    unsigned aHbase = (unsigned)__cvta_generic_to_shared(sAh + aRow * PAD_);
    unsigned aLbase = (unsigned)__cvta_generic_to_shared(sAl + aRow * PAD_);
    unsigned wHbase = (unsigned)__cvta_generic_to_shared(sWh);
    unsigned wLbase = (unsigned)__cvta_generic_to_shared(sWl);

    #pragma unroll
    for (int kc = 0; kc < 8; kc++) {
        int k0 = kc * 16;
        unsigned ah[2][4], al[2][4];
        #pragma unroll
        for (int mt = 0; mt < 2; mt++) {
            unsigned off = (mt * 16 * PAD_ + k0 + aColAdd) * 2;
            ldsm4(ah[mt][0], ah[mt][1], ah[mt][2], ah[mt][3], aHbase + off);
            ldsm4(al[mt][0], al[mt][1], al[mt][2], al[mt][3], aLbase + off);
        }
        #pragma unroll
        for (int nt2 = 0; nt2 < 4; nt2++) {   // 16 cols each
            int nb = nbase + nt2 * 16;
            unsigned off = ((k0 + bRowAdd) * PAD_ + nb + bColAdd) * 2;
            unsigned bh[4], bl[4];
            ldsm4t(bh[0], bh[1], bh[2], bh[3], wHbase + off);
            ldsm4t(bl[0], bl[1], bl[2], bl[3], wLbase + off);
            #pragma unroll
            for (int mt = 0; mt < 2; mt++) {
                // n-tile 0 of this 16-col group
                mma16816(acc[mt][nt2 * 2],     ah[mt], bh);
                mma16816(acc[mt][nt2 * 2],     al[mt], bh);
                mma16816(acc[mt][nt2 * 2],     ah[mt], bl);
                // n-tile 1
                mma16816(acc[mt][nt2 * 2 + 1], ah[mt], bh + 2);
                mma16816(acc[mt][nt2 * 2 + 1], al[mt], bh + 2);
                mma16816(acc[mt][nt2 * 2 + 1], ah[mt], bl + 2);
            }
        }
    }

    // epilogue
    const float* Bt = Bbase + t * D_;
    float alpha = 0.f, beta = 0.f;
    if (outop == 2) { alpha = 1.f / (1.f + expf(-skipv[t])); beta = 1.f - alpha; }

    int rq = lane >> 2, cq = (lane & 3) * 2;
    #pragma unroll
    for (int mt = 0; mt < 2; mt++) {
        int rl0 = mbase + mt * 16 + rq;
        #pragma unroll
        for (int nt = 0; nt < 8; nt++) {
            int col = nbase + nt * 8 + cq;
            float b0 = Bt[col], b1 = Bt[col + 1];
            float* a = acc[mt][nt];
            #pragma unroll
            for (int half = 0; half < 2; half++) {
                int rl = rl0 + half * 8;
                if (rl < rem) {
                    int grow = sList[rl];
                    float* op = out + (size_t)grow * D_ + col;
                    float v0 = a[half * 2]     + b0;
                    float v1 = a[half * 2 + 1] + b1;
                    if (outop == 1) { v0 = tanhf(v0); v1 = tanhf(v1); }
                    else if (outop == 2) {
                        float2 old = *(float2*)op;
                        v0 = alpha * v0 + beta * old.x;
                        v1 = alpha * v1 + beta * old.y;
                    }
                    *(float2*)op = make_float2(v0, v1);
                }
            }
        }
    }
}

// ---------------- edge pass A: scores + segment max ----------------
__global__ void __launch_bounds__(256) k_edgeA(const float* __restrict__ relAtt,
                                               const float* __restrict__ relPri) {
    int r = blockIdx.y;
    __shared__ float sA[H_ * 260];
    const float* Ar = relAtt + r * H_ * 256;
    for (int i = threadIdx.x; i < H_ * 256; i += blockDim.x)
        sA[(i >> 8) * 260 + (i & 255)] = Ar[i];
    __syncthreads();

    int lo = g_rOff[r], hi = g_rOff[r + 1];
    int lane = threadIdx.x & 31;
    int h = lane & 7, esub = lane >> 3;
    int warp = blockIdx.x * (blockDim.x >> 5) + (threadIdx.x >> 5);
    int nwarp = gridDim.x * (blockDim.x >> 5);
    const float* A = sA + h * 260;

    for (int eb = lo + warp * 4; eb < hi; eb += nwarp * 4) {
        int p = eb + esub;
        bool valid = p < hi;
        if (!valid) p = lo;
        int s = g_eS[p], t = g_eT[p], meta = g_eMeta[p], e = g_eId[p];
        int st = meta & 3, tt = (meta >> 2) & 3, tm = meta >> 4;

        const float* kp = g_Kn + (size_t)s * D_ + h * 16;
        const float* tp = g_tabK + (size_t)(st * ML_ + tm) * 128 + h * 16;
        float kr[16];
        #pragma unroll
        for (int q4 = 0; q4 < 4; q4++) {
            float4 a = *(const float4*)(kp + q4 * 4);
            float4 b = *(const float4*)(tp + q4 * 4);
            kr[q4 * 4 + 0] = a.x + b.x; kr[q4 * 4 + 1] = a.y + b.y;
            kr[q4 * 4 + 2] = a.z + b.z; kr[q4 * 4 + 3] = a.w + b.w;
        }
        float acc[16];
        #pragma unroll
        for (int j = 0; j < 16; j++) acc[j] = 0.f;
        #pragma unroll
        for (int kk = 0; kk < 16; kk++) {
            float kv = kr[kk];
            const float4* ap = (const float4*)(A + kk * 16);
            float4 a0 = ap[0], a1 = ap[1], a2 = ap[2], a3 = ap[3];
            acc[0]  += kv * a0.x; acc[1]  += kv * a0.y; acc[2]  += kv * a0.z; acc[3]  += kv * a0.w;
            acc[4]  += kv * a1.x; acc[5]  += kv * a1.y; acc[6]  += kv * a1.z; acc[7]  += kv * a1.w;
            acc[8]  += kv * a2.x; acc[9]  += kv * a2.y; acc[10] += kv * a2.z; acc[11] += kv * a2.w;
            acc[12] += kv * a3.x; acc[13] += kv * a3.y; acc[14] += kv * a3.z; acc[15] += kv * a3.w;
        }
        const float4* qp = (const float4*)(g_Qn + (size_t)t * D_ + h * 16);
        float4 q0 = qp[0], q1 = qp[1], q2 = qp[2], q3 = qp[3];
        float sc = q0.x * acc[0]  + q0.y * acc[1]  + q0.z * acc[2]  + q0.w * acc[3]
                 + q1.x * acc[4]  + q1.y * acc[5]  + q1.z * acc[6]  + q1.w * acc[7]
                 + q2.x * acc[8]  + q2.y * acc[9]  + q2.z * acc[10] + q2.w * acc[11]
                 + q3.x * acc[12] + q3.y * acc[13] + q3.z * acc[14] + q3.w * acc[15];
        float pri = relPri[((tt * R_ + r) * T_ + st) * H_ + h];
        sc *= pri * 0.25f;
        if (valid) {
            g_score[(size_t)e * H_ + h] = sc;
            atomicMax(&g_mx[t * H_ + h], fmap(sc));
        }
    }
}

__global__ void k_edgeB(const int* __restrict__ tgt) {
    int idx = blockIdx.x * blockDim.x + threadIdx.x;
    if (idx >= E_ * H_) return;
    int e = idx >> 3, h = idx & 7;
    int t = tgt[e];
    float m = funmap(g_mx[t * H_ + h]);
    float ex = expf(g_score[idx] - m);
    g_score[idx] = ex;
    atomicAdd(&g_den[t * H_ + h], ex);
}

__global__ void __launch_bounds__(256) k_edgeC(const float* __restrict__ relMsg) {
    int r = blockIdx.y;
    __shared__ float sA[H_ * 260];
    const float* Ar = relMsg + r * H_ * 256;
    for (int i = threadIdx.x; i < H_ * 256; i += blockDim.x)
        sA[(i >> 8) * 260 + (i & 255)] = Ar[i];
    __syncthreads();

    int lo = g_rOff[r], hi = g_rOff[r + 1];
    int lane = threadIdx.x & 31;
    int h = lane & 7, esub = lane >> 3;
    int warp = blockIdx.x * (blockDim.x >> 5) + (threadIdx.x >> 5);
    int nwarp = gridDim.x * (blockDim.x >> 5);
    const float* A = sA + h * 260;

    for (int eb = lo + warp * 4; eb < hi; eb += nwarp * 4) {
        int p = eb + esub;
        bool valid = p < hi;
        if (!valid) p = lo;
        int s = g_eS[p], t = g_eT[p], meta = g_eMeta[p], e = g_eId[p];
        int st = meta & 3, tm = meta >> 4;

        const float* vp = g_Vn + (size_t)s * D_ + h * 16;
        const float* tp = g_tabV + (size_t)(st * ML_ + tm) * 128 + h * 16;
        float vr[16];
        #pragma unroll
        for (int q4 = 0; q4 < 4; q4++) {
            float4 a = *(const float4*)(vp + q4 * 4);
            float4 b = *(const float4*)(tp + q4 * 4);
            vr[q4 * 4 + 0] = a.x + b.x; vr[q4 * 4 + 1] = a.y + b.y;
            vr[q4 * 4 + 2] = a.z + b.z; vr[q4 * 4 + 3] = a.w + b.w;
        }
        float acc[16];
        #pragma unroll
        for (int j = 0; j < 16; j++) acc[j] = 0.f;
        #pragma unroll
        for (int kk = 0; kk < 16; kk++) {
            float kv = vr[kk];
            const float4* ap = (const float4*)(A + kk * 16);
            float4 a0 = ap[0], a1 = ap[1], a2 = ap[2], a3 = ap[3];
            acc[0]  += kv * a0.x; acc[1]  += kv * a0.y; acc[2]  += kv * a0.z; acc[3]  += kv * a0.w;
            acc[4]  += kv * a1.x; acc[5]  += kv * a1.y; acc[6]  += kv * a1.z; acc[7]  += kv * a1.w;
            acc[8]  += kv * a2.x; acc[9]  += kv * a2.y; acc[10] += kv * a2.z; acc[11] += kv * a2.w;
            acc[12] += kv * a3.x; acc[13] += kv * a3.y; acc[14] += kv * a3.z; acc[15] += kv * a3.w;
        }
        float ex = g_score[(size_t)e * H_ + h];
        float den = g_den[t * H_ + h];
        float att = ex / den;
        if (valid) {
            float* op = g_aggr + (size_t)t * D_ + h * 16;
            red_add_v4(op,      acc[0] * att,  acc[1] * att,  acc[2] * att,  acc[3] * att);
            red_add_v4(op + 4,  acc[4] * att,  acc[5] * att,  acc[6] * att,  acc[7] * att);
            red_add_v4(op + 8,  acc[8] * att,  acc[9] * att,  acc[10] * att, acc[11] * att);
            red_add_v4(op + 12, acc[12] * att, acc[13] * att, acc[14] * att, acc[15] * att);
        }
    }
}

__global__ void k_out(float* __restrict__ o) {
    int i = blockIdx.x * blockDim.x + threadIdx.x;
    int n4 = (int)(TD_ / 4);
    if (i < n4) ((float4*)o)[i] = ((const float4*)g_x)[i];
}

extern "C" void kernel_launch(void* const* d_in, const int* in_sizes, int n_in,
                              void* d_out, int out_size) {
    const float* node_feature = (const float*)d_in[0];
    const int*   node_type    = (const int*)d_in[1];
    const int*   edge_index   = (const int*)d_in[2];
    const int*   edge_type    = (const int*)d_in[3];
    const int*   edge_time    = (const int*)d_in[4];
    const float* adapt_w      = (const float*)d_in[5];
    const float* adapt_b      = (const float*)d_in[6];
    const float* Wk           = (const float*)d_in[7];
    const float* bk           = (const float*)d_in[8];
    const float* Wq           = (const float*)d_in[9];
    const float* bq           = (const float*)d_in[10];
    const float* Wv           = (const float*)d_in[11];
    const float* bv           = (const float*)d_in[12];
    const float* Wa           = (const float*)d_in[13];
    const float* ba           = (const float*)d_in[14];
    const float* rel_pri      = (const float*)d_in[15];
    const float* rel_att      = (const float*)d_in[16];
    const float* rel_msg      = (const float*)d_in[17];
    const float* skip         = (const float*)d_in[18];
    const float* rte_w        = (const float*)d_in[19];
    const float* rte_b        = (const float*)d_in[20];

    const int* src = edge_index;
    const int* tgt = edge_index + E_;

    float *px, *pq, *pk, *pv, *pa;
    cudaGetSymbolAddress((void**)&px, g_x);
    cudaGetSymbolAddress((void**)&pq, g_Qn);
    cudaGetSymbolAddress((void**)&pk, g_Kn);
    cudaGetSymbolAddress((void**)&pv, g_Vn);
    cudaGetSymbolAddress((void**)&pa, g_aggr);

    cudaFuncSetAttribute(k_typed_gemm, cudaFuncAttributeMaxDynamicSharedMemorySize, GEMM_SMEM);

    k_rte_tab<<<ML_, 128>>>();
    k_init_once<<<1, 32>>>();
    k_build_type<<<(N_ + 255) / 256, 256>>>(node_type);
    k_count_r<<<(E_ + 255) / 256, 256>>>(edge_type);
    k_scan_r<<<1, 1>>>();
    k_scatter_r<<<(E_ + 255) / 256, 256>>>(src, tgt, edge_type, edge_time, node_type);

    dim3 ggrid((N_ + 127) / 128, T_);
    dim3 egrid(128, R_);

    // x = tanh(typed_linear(node_feature; adapt))
    k_typed_gemm<<<ggrid, 256, GEMM_SMEM>>>(0, 1, node_feature, adapt_w, adapt_b, px, nullptr);

    for (int l = 0; l < 2; l++) {
        size_t woff = (size_t)l * T_ * 128 * 128;
        size_t boff = (size_t)l * T_ * 128;
        k_rte_proj<<<ML_, 128>>>(rte_w + (size_t)l * 256 * 128, rte_b + (size_t)l * 128);
        k_tables<<<T_ * ML_, 128>>>(Wk + woff, Wv + woff);

        k_typed_gemm<<<ggrid, 256, GEMM_SMEM>>>(0, 0, px, Wq + woff, bq + boff, pq, nullptr);
        k_typed_gemm<<<ggrid, 256, GEMM_SMEM>>>(0, 0, px, Wk + woff, bk + boff, pk, nullptr);
        k_typed_gemm<<<ggrid, 256, GEMM_SMEM>>>(0, 0, px, Wv + woff, bv + boff, pv, nullptr);

        k_init_layer<<<2048, 256>>>();
        k_edgeA<<<egrid, 256>>>(rel_att + (size_t)l * R_ * H_ * 256,
                                rel_pri + (size_t)l * T_ * R_ * T_ * H_);
        k_edgeB<<<(E_ * H_ + 255) / 256, 256>>>(tgt);
        k_edgeC<<<egrid, 256>>>(rel_msg + (size_t)l * R_ * H_ * 256);

        // x = alpha * typed_linear(gelu(aggr); Wa) + (1-alpha) * x
        k_typed_gemm<<<ggrid, 256, GEMM_SMEM>>>(1, 2, pa, Wa + woff, ba + boff, px, skip + (size_t)l * T_);
    }

    k_out<<<(int)((TD_ / 4 + 255) / 256), 256>>>((float*)d_out);
}

// round 4
// speedup vs baseline: 1.2432x; 1.1278x over previous
#include <cuda_runtime.h>
#include <cuda_bf16.h>
#include <math.h>

#define N_ 100000
#define E_ 500000
#define D_ 128
#define T_ 3
#define R_ 4
#define H_ 8
#define ML_ 240
#define TD_ ((size_t)N_*(size_t)D_)
#define PAD_ 136                        // bf16 elems per smem row (272B stride)
#define GEMM_SMEM (4 * 128 * PAD_ * 2)  // Ahi, Alo, Whi, Wlo
#define NMAT_ 9                         // adapt + (q,k,v,a) x 2 layers

__device__ float g_x[TD_];
__device__ float g_Qn[TD_];
__device__ float g_Kn[TD_];
__device__ float g_Vn[TD_];
__device__ float g_aggr[TD_];
__device__ float g_score[(size_t)E_*H_];
__device__ int   g_mx[N_*H_];
__device__ float g_den[N_*H_];
__device__ float g_rte_tab[ML_*2*D_];
__device__ float g_rte_proj[ML_*D_];
__device__ float g_tabK[2][T_*ML_*D_];
__device__ float g_tabV[2][T_*ML_*D_];
__device__ __nv_bfloat16 g_Wh[(size_t)NMAT_*T_*D_*D_];
__device__ __nv_bfloat16 g_Wl[(size_t)NMAT_*T_*D_*D_];
__device__ int   g_typeList[T_][N_];
__device__ int   g_typeCnt[T_];
__device__ int   g_rCnt[R_];
__device__ int   g_rOff[R_+1];
__device__ int   g_rFill[R_];
__device__ int   g_eS[E_];
__device__ int   g_eT[E_];
__device__ int   g_eMeta[E_];   // st | tt<<2 | time<<4

__device__ __forceinline__ int fmap(float f) {
    int i = __float_as_int(f);
    return i >= 0 ? i : (i ^ 0x7fffffff);
}
__device__ __forceinline__ float funmap(int i) {
    return __int_as_float(i >= 0 ? i : (i ^ 0x7fffffff));
}
__device__ __forceinline__ float gelu_f(float x) { return x * normcdff(x); }

__device__ __forceinline__ void red_add_v4(float* p, float a, float b, float c, float d) {
    asm volatile("red.global.add.v4.f32 [%0], {%1,%2,%3,%4};"
                 :: "l"(p), "f"(a), "f"(b), "f"(c), "f"(d) : "memory");
}

// ---------------- mma helpers ----------------
__device__ __forceinline__ void ldsm4(unsigned& r0, unsigned& r1, unsigned& r2, unsigned& r3,
                                      unsigned addr) {
    asm volatile("ldmatrix.sync.aligned.m8n8.x4.shared.b16 {%0,%1,%2,%3}, [%4];"
                 : "=r"(r0), "=r"(r1), "=r"(r2), "=r"(r3) : "r"(addr));
}
__device__ __forceinline__ void ldsm4t(unsigned& r0, unsigned& r1, unsigned& r2, unsigned& r3,
                                       unsigned addr) {
    asm volatile("ldmatrix.sync.aligned.m8n8.x4.trans.shared.b16 {%0,%1,%2,%3}, [%4];"
                 : "=r"(r0), "=r"(r1), "=r"(r2), "=r"(r3) : "r"(addr));
}
__device__ __forceinline__ void mma16816(float* d, const unsigned* a, const unsigned* b) {
    asm volatile("mma.sync.aligned.m16n8k16.row.col.f32.bf16.bf16.f32 "
                 "{%0,%1,%2,%3}, {%4,%5,%6,%7}, {%8,%9}, {%0,%1,%2,%3};"
                 : "+f"(d[0]), "+f"(d[1]), "+f"(d[2]), "+f"(d[3])
                 : "r"(a[0]), "r"(a[1]), "r"(a[2]), "r"(a[3]), "r"(b[0]), "r"(b[1]));
}
__device__ __forceinline__ unsigned pack_bf2(__nv_bfloat16 a, __nv_bfloat16 b) {
    __nv_bfloat162 p(a, b);
    return *reinterpret_cast<unsigned*>(&p);
}

// ---------------- precompute kernels ----------------
__global__ void k_rte_tab() {
    int pos = blockIdx.x;
    int i   = threadIdx.x;
    const float s = 0.08838834764831845f;
    float div;
    if (i >= 5) div = 0.f;   // fp32 10000^ar overflow -> inf -> 0
    else {
        float pf = (float)pow(10000.0, (double)(2 * i));
        div = 1.0f / ((pf / 128.0f) / 2.0f);
    }
    float ang = (float)pos * div;
    double a = (double)ang;
    g_rte_tab[pos * 256 + 2 * i]     = (float)sin(a) * s;
    g_rte_tab[pos * 256 + 2 * i + 1] = (float)cos(a) * s;
}

__global__ void k_rte_proj(const float* __restrict__ w, const float* __restrict__ b) {
    int time = blockIdx.x;
    int d    = threadIdx.x;
    float acc = b[d];
    const float* tr = g_rte_tab + time * 256;
    for (int c = 0; c < 256; c++) acc += tr[c] * w[c * 128 + d];
    g_rte_proj[time * 128 + d] = acc;
}

__global__ void k_tables(const float* __restrict__ Wk, const float* __restrict__ Wv, int l) {
    int id = blockIdx.x;
    int d  = threadIdx.x;
    int t = id / ML_, time = id % ML_;
    const float* pr = g_rte_proj + time * 128;
    const float* wk = Wk + (size_t)t * 128 * 128;
    const float* wv = Wv + (size_t)t * 128 * 128;
    float aK = 0.f, aV = 0.f;
    for (int k = 0; k < 128; k++) {
        float p = pr[k];
        aK += p * wk[k * 128 + d];
        aV += p * wv[k * 128 + d];
    }
    g_tabK[l][(t * ML_ + time) * 128 + d] = aK;
    g_tabV[l][(t * ML_ + time) * 128 + d] = aV;
}

// split a typed weight tensor (T x 128 x 128 fp32) into bf16 hi/lo at slot midx
__global__ void k_wsplit(const float* __restrict__ src, int midx) {
    int i = blockIdx.x * blockDim.x + threadIdx.x;
    int n = T_ * D_ * D_;
    if (i >= n) return;
    size_t off = (size_t)midx * n + i;
    float v = src[i];
    __nv_bfloat16 h = __float2bfloat16_rn(v);
    g_Wh[off] = h;
    g_Wl[off] = __float2bfloat16_rn(v - __bfloat162float(h));
}

// ---------------- bucketing (block-aggregated atomics) ----------------
__global__ void k_init_once() {
    int i = threadIdx.x;
    if (i < T_) g_typeCnt[i] = 0;
    if (i < R_) { g_rCnt[i] = 0; g_rFill[i] = 0; }
}

__global__ void k_build_type(const int* __restrict__ nt) {
    __shared__ int c[T_];
    __shared__ int base[T_];
    int tid = threadIdx.x;
    if (tid < T_) c[tid] = 0;
    __syncthreads();
    int i = blockIdx.x * blockDim.x + tid;
    int t = -1, rank = 0;
    if (i < N_) { t = nt[i]; rank = atomicAdd(&c[t], 1); }
    __syncthreads();
    if (tid < T_) base[tid] = c[tid] ? atomicAdd(&g_typeCnt[tid], c[tid]) : 0;
    __syncthreads();
    if (i < N_) g_typeList[t][base[t] + rank] = i;
}

__global__ void k_count_r(const int* __restrict__ et) {
    __shared__ int c[R_];
    int tid = threadIdx.x;
    if (tid < R_) c[tid] = 0;
    __syncthreads();
    int i = blockIdx.x * blockDim.x + tid;
    if (i < E_) atomicAdd(&c[et[i]], 1);
    __syncthreads();
    if (tid < R_ && c[tid]) atomicAdd(&g_rCnt[tid], c[tid]);
}

__global__ void k_scan_r() {
    g_rOff[0] = 0;
    for (int r = 0; r < R_; r++) g_rOff[r + 1] = g_rOff[r] + g_rCnt[r];
}

__global__ void k_scatter_r(const int* __restrict__ src, const int* __restrict__ tgt,
                            const int* __restrict__ et, const int* __restrict__ etm,
                            const int* __restrict__ nt) {
    __shared__ int c[R_];
    __shared__ int base[R_];
    int tid = threadIdx.x;
    if (tid < R_) c[tid] = 0;
    __syncthreads();
    int e = blockIdx.x * blockDim.x + tid;
    int r = -1, rank = 0;
    if (e < E_) { r = et[e]; rank = atomicAdd(&c[r], 1); }
    __syncthreads();
    if (tid < R_) base[tid] = c[tid] ? atomicAdd(&g_rFill[tid], c[tid]) : 0;
    __syncthreads();
    if (e < E_) {
        int p = g_rOff[r] + base[r] + rank;
        int s = src[e], t = tgt[e];
        g_eS[p] = s;
        g_eT[p] = t;
        g_eMeta[p] = nt[s] | (nt[t] << 2) | (etm[e] << 4);
    }
}

__global__ void k_init_layer() {
    int stride = gridDim.x * blockDim.x;
    int i0 = blockIdx.x * blockDim.x + threadIdx.x;
    for (int i = i0; i < N_ * H_; i += stride) { g_mx[i] = 0x807FFFFF; g_den[i] = 0.f; }
    for (size_t i = i0; i < TD_; i += (size_t)stride) g_aggr[i] = 0.f;
}

// ---------------- GEMM building blocks ----------------
// load pre-split bf16 W (slot midx, type t) into padded smem buffers
__device__ __forceinline__ void load_w_smem(__nv_bfloat16* sWh, __nv_bfloat16* sWl,
                                            int midx, int t, int tid) {
    size_t base = ((size_t)midx * T_ + t) * D_ * D_;
    const uint4* wh4 = (const uint4*)(g_Wh + base);
    const uint4* wl4 = (const uint4*)(g_Wl + base);
    #pragma unroll
    for (int it = 0; it < 8; it++) {
        int idx = it * 256 + tid;          // uint4 index over 128x128 bf16 (2048)
        int row = idx >> 4;
        int col = (idx & 15) * 8;
        *(uint4*)(sWh + row * PAD_ + col) = wh4[idx];
        *(uint4*)(sWl + row * PAD_ + col) = wl4[idx];
    }
}

// load+convert gathered A tile (fp32 -> bf16 hi/lo), optional gelu
__device__ __forceinline__ void load_a_smem(__nv_bfloat16* sAh, __nv_bfloat16* sAl,
                                            const float* __restrict__ in,
                                            const int* sList, int inop, int tid) {
    #pragma unroll
    for (int it = 0; it < 16; it++) {
        int idx = it * 256 + tid;          // float4 index, 0..4095
        int row = idx >> 5;
        int col = (idx & 31) << 2;
        int grow = sList[row];
        float4 v = *(const float4*)(in + (size_t)grow * D_ + col);
        if (inop == 1) {
            v.x = gelu_f(v.x); v.y = gelu_f(v.y); v.z = gelu_f(v.z); v.w = gelu_f(v.w);
        }
        __nv_bfloat16 h0 = __float2bfloat16_rn(v.x), h1 = __float2bfloat16_rn(v.y);
        __nv_bfloat16 h2 = __float2bfloat16_rn(v.z), h3 = __float2bfloat16_rn(v.w);
        __nv_bfloat16 l0 = __float2bfloat16_rn(v.x - __bfloat162float(h0));
        __nv_bfloat16 l1 = __float2bfloat16_rn(v.y - __bfloat162float(h1));
        __nv_bfloat16 l2 = __float2bfloat16_rn(v.z - __bfloat162float(h2));
        __nv_bfloat16 l3 = __float2bfloat16_rn(v.w - __bfloat162float(h3));
        *(uint2*)(sAh + row * PAD_ + col) = make_uint2(pack_bf2(h0, h1), pack_bf2(h2, h3));
        *(uint2*)(sAl + row * PAD_ + col) = make_uint2(pack_bf2(l0, l1), pack_bf2(l2, l3));
    }
}

// 3-term split MMA over the resident tiles
__device__ __forceinline__ void mma_tile(float (&acc)[2][8][4],
                                         const __nv_bfloat16* sAh, const __nv_bfloat16* sAl,
                                         const __nv_bfloat16* sWh, const __nv_bfloat16* sWl,
                                         int mbase, int nbase, int lane) {
    int aRow = mbase + (lane & 15);
    int aColAdd = (lane >> 4) << 3;
    int bg = lane >> 3;
    int bRowAdd = ((bg & 1) << 3) + (lane & 7);
    int bColAdd = (bg >> 1) << 3;

    unsigned aHbase = (unsigned)__cvta_generic_to_shared(sAh + aRow * PAD_);
    unsigned aLbase = (unsigned)__cvta_generic_to_shared(sAl + aRow * PAD_);
    unsigned wHbase = (unsigned)__cvta_generic_to_shared(sWh);
    unsigned wLbase = (unsigned)__cvta_generic_to_shared(sWl);

    #pragma unroll
    for (int kc = 0; kc < 8; kc++) {
        int k0 = kc * 16;
        unsigned ah[2][4], al[2][4];
        #pragma unroll
        for (int mt = 0; mt < 2; mt++) {
            unsigned off = (mt * 16 * PAD_ + k0 + aColAdd) * 2;
            ldsm4(ah[mt][0], ah[mt][1], ah[mt][2], ah[mt][3], aHbase + off);
            ldsm4(al[mt][0], al[mt][1], al[mt][2], al[mt][3], aLbase + off);
        }
        #pragma unroll
        for (int nt2 = 0; nt2 < 4; nt2++) {
            int nb = nbase + nt2 * 16;
            unsigned off = ((k0 + bRowAdd) * PAD_ + nb + bColAdd) * 2;
            unsigned bh[4], bl[4];
            ldsm4t(bh[0], bh[1], bh[2], bh[3], wHbase + off);
            ldsm4t(bl[0], bl[1], bl[2], bl[3], wLbase + off);
            #pragma unroll
            for (int mt = 0; mt < 2; mt++) {
                mma16816(acc[mt][nt2 * 2],     ah[mt], bh);
                mma16816(acc[mt][nt2 * 2],     al[mt], bh);
                mma16816(acc[mt][nt2 * 2],     ah[mt], bl);
                mma16816(acc[mt][nt2 * 2 + 1], ah[mt], bh + 2);
                mma16816(acc[mt][nt2 * 2 + 1], al[mt], bh + 2);
                mma16816(acc[mt][nt2 * 2 + 1], ah[mt], bl + 2);
            }
        }
    }
}

// plain bias epilogue (outop 0)
__device__ __forceinline__ void epi_bias(float (&acc)[2][8][4], const float* Bt,
                                         float* out, const int* sList, int rem,
                                         int mbase, int nbase, int lane) {
    int rq = lane >> 2, cq = (lane & 3) * 2;
    #pragma unroll
    for (int mt = 0; mt < 2; mt++) {
        int rl0 = mbase + mt * 16 + rq;
        #pragma unroll
        for (int nt = 0; nt < 8; nt++) {
            int col = nbase + nt * 8 + cq;
            float b0 = Bt[col], b1 = Bt[col + 1];
            float* a = acc[mt][nt];
            #pragma unroll
            for (int half = 0; half < 2; half++) {
                int rl = rl0 + half * 8;
                if (rl < rem) {
                    int grow = sList[rl];
                    float* op = out + (size_t)grow * D_ + col;
                    *(float2*)op = make_float2(a[half * 2] + b0, a[half * 2 + 1] + b1);
                }
            }
        }
    }
}

// ---------------- fused QKV GEMM ----------------
__global__ void __launch_bounds__(256) k_qkv_gemm(
    const float* __restrict__ in, int midx0,
    const float* __restrict__ Bq, const float* __restrict__ Bk, const float* __restrict__ Bv,
    float* __restrict__ Oq, float* __restrict__ Ok, float* __restrict__ Ov)
{
    int t = blockIdx.y;
    int cnt = g_typeCnt[t];
    int base = blockIdx.x * 128;
    if (base >= cnt) return;
    const int* list = &g_typeList[t][base];
    int rem = cnt - base; if (rem > 128) rem = 128;

    extern __shared__ __nv_bfloat16 sm[];
    __nv_bfloat16* sAh = sm;
    __nv_bfloat16* sAl = sAh + 128 * PAD_;
    __nv_bfloat16* sWh = sAl + 128 * PAD_;
    __nv_bfloat16* sWl = sWh + 128 * PAD_;
    __shared__ int sList[128];

    int tid = threadIdx.x;
    if (tid < 128) sList[tid] = (tid < rem) ? list[tid] : list[0];
    __syncthreads();

    load_a_smem(sAh, sAl, in, sList, 0, tid);

    int warp = tid >> 5, lane = tid & 31;
    int mbase = (warp & 3) * 32;
    int nbase = (warp >> 2) * 64;

    #pragma unroll
    for (int s = 0; s < 3; s++) {
        if (s > 0) __syncthreads();           // prior stage's smem reads done
        load_w_smem(sWh, sWl, midx0 + s, t, tid);
        __syncthreads();

        float acc[2][8][4];
        #pragma unroll
        for (int i = 0; i < 2; i++)
            #pragma unroll
            for (int j = 0; j < 8; j++)
                #pragma unroll
                for (int q = 0; q < 4; q++) acc[i][j][q] = 0.f;

        mma_tile(acc, sAh, sAl, sWh, sWl, mbase, nbase, lane);

        const float* Bt = (s == 0 ? Bq : s == 1 ? Bk : Bv) + t * D_;
        float* out = (s == 0 ? Oq : s == 1 ? Ok : Ov);
        epi_bias(acc, Bt, out, sList, rem, mbase, nbase, lane);
    }
}

// ---------------- single typed GEMM (adapt / trans) ----------------
// inop: 0=none, 1=gelu. outop: 1=tanh, 2=skip-mix (out = a*v + (1-a)*prev)
__global__ void __launch_bounds__(256) k_typed_gemm(
    int inop, int outop,
    const float* __restrict__ in, int midx,
    const float* __restrict__ Bbase,
    float* __restrict__ out,
    const float* __restrict__ prev,
    const float* __restrict__ skipv)
{
    int t = blockIdx.y;
    int cnt = g_typeCnt[t];
    int base = blockIdx.x * 128;
    if (base >= cnt) return;
    const int* list = &g_typeList[t][base];
    int rem = cnt - base; if (rem > 128) rem = 128;

    extern __shared__ __nv_bfloat16 sm[];
    __nv_bfloat16* sAh = sm;
    __nv_bfloat16* sAl = sAh + 128 * PAD_;
    __nv_bfloat16* sWh = sAl + 128 * PAD_;
    __nv_bfloat16* sWl = sWh + 128 * PAD_;
    __shared__ int sList[128];

    int tid = threadIdx.x;
    if (tid < 128) sList[tid] = (tid < rem) ? list[tid] : list[0];
    __syncthreads();

    load_a_smem(sAh, sAl, in, sList, inop, tid);
    load_w_smem(sWh, sWl, midx, t, tid);
    __syncthreads();

    int warp = tid >> 5, lane = tid & 31;
    int mbase = (warp & 3) * 32;
    int nbase = (warp >> 2) * 64;

    float acc[2][8][4];
    #pragma unroll
    for (int i = 0; i < 2; i++)
        #pragma unroll
        for (int j = 0; j < 8; j++)
            #pragma unroll
            for (int q = 0; q < 4; q++) acc[i][j][q] = 0.f;

    mma_tile(acc, sAh, sAl, sWh, sWl, mbase, nbase, lane);

    const float* Bt = Bbase + t * D_;
    float alpha = 0.f, beta = 0.f;
    if (outop == 2) { alpha = 1.f / (1.f + expf(-skipv[t])); beta = 1.f - alpha; }

    int rq = lane >> 2, cq = (lane & 3) * 2;
    #pragma unroll
    for (int mt = 0; mt < 2; mt++) {
        int rl0 = mbase + mt * 16 + rq;
        #pragma unroll
        for (int nt = 0; nt < 8; nt++) {
            int col = nbase + nt * 8 + cq;
            float b0 = Bt[col], b1 = Bt[col + 1];
            float* a = acc[mt][nt];
            #pragma unroll
            for (int half = 0; half < 2; half++) {
                int rl = rl0 + half * 8;
                if (rl < rem) {
                    int grow = sList[rl];
                    float v0 = a[half * 2]     + b0;
                    float v1 = a[half * 2 + 1] + b1;
                    if (outop == 1) { v0 = tanhf(v0); v1 = tanhf(v1); }
                    else {
                        const float* pp = prev + (size_t)grow * D_ + col;
                        float2 old = *(const float2*)pp;
                        v0 = alpha * v0 + beta * old.x;
                        v1 = alpha * v1 + beta * old.y;
                    }
                    *(float2*)(out + (size_t)grow * D_ + col) = make_float2(v0, v1);
                }
            }
        }
    }
}

// ---------------- edge pass A: scores + segment max ----------------
__global__ void __launch_bounds__(256) k_edgeA(const float* __restrict__ relAtt,
                                               const float* __restrict__ relPri, int layer) {
    int r = blockIdx.y;
    __shared__ float sA[H_ * 260];
    const float* Ar = relAtt + r * H_ * 256;
    for (int i = threadIdx.x; i < H_ * 256; i += blockDim.x)
        sA[(i >> 8) * 260 + (i & 255)] = Ar[i];
    __syncthreads();

    int lo = g_rOff[r], hi = g_rOff[r + 1];
    int lane = threadIdx.x & 31;
    int h = lane & 7, esub = lane >> 3;
    int warp = blockIdx.x * (blockDim.x >> 5) + (threadIdx.x >> 5);
    int nwarp = gridDim.x * (blockDim.x >> 5);
    const float* A = sA + h * 260;
    const float* tab = g_tabK[layer];

    for (int eb = lo + warp * 4; eb < hi; eb += nwarp * 4) {
        int p = eb + esub;
        bool valid = p < hi;
        if (!valid) p = lo;
        int s = g_eS[p], t = g_eT[p], meta = g_eMeta[p];
        int st = meta & 3, tt = (meta >> 2) & 3, tm = meta >> 4;

        const float* kp = g_Kn + (size_t)s * D_ + h * 16;
        const float* tp = tab + (size_t)(st * ML_ + tm) * 128 + h * 16;
        float kr[16];
        #pragma unroll
        for (int q4 = 0; q4 < 4; q4++) {
            float4 a = *(const float4*)(kp + q4 * 4);
            float4 b = *(const float4*)(tp + q4 * 4);
            kr[q4 * 4 + 0] = a.x + b.x; kr[q4 * 4 + 1] = a.y + b.y;
            kr[q4 * 4 + 2] = a.z + b.z; kr[q4 * 4 + 3] = a.w + b.w;
        }
        float acc[16];
        #pragma unroll
        for (int j = 0; j < 16; j++) acc[j] = 0.f;
        #pragma unroll
        for (int kk = 0; kk < 16; kk++) {
            float kv = kr[kk];
            const float4* ap = (const float4*)(A + kk * 16);
            float4 a0 = ap[0], a1 = ap[1], a2 = ap[2], a3 = ap[3];
            acc[0]  += kv * a0.x; acc[1]  += kv * a0.y; acc[2]  += kv * a0.z; acc[3]  += kv * a0.w;
            acc[4]  += kv * a1.x; acc[5]  += kv * a1.y; acc[6]  += kv * a1.z; acc[7]  += kv * a1.w;
            acc[8]  += kv * a2.x; acc[9]  += kv * a2.y; acc[10] += kv * a2.z; acc[11] += kv * a2.w;
            acc[12] += kv * a3.x; acc[13] += kv * a3.y; acc[14] += kv * a3.z; acc[15] += kv * a3.w;
        }
        const float4* qp = (const float4*)(g_Qn + (size_t)t * D_ + h * 16);
        float4 q0 = qp[0], q1 = qp[1], q2 = qp[2], q3 = qp[3];
        float sc = q0.x * acc[0]  + q0.y * acc[1]  + q0.z * acc[2]  + q0.w * acc[3]
                 + q1.x * acc[4]  + q1.y * acc[5]  + q1.z * acc[6]  + q1.w * acc[7]
                 + q2.x * acc[8]  + q2.y * acc[9]  + q2.z * acc[10] + q2.w * acc[11]
                 + q3.x * acc[12] + q3.y * acc[13] + q3.z * acc[14] + q3.w * acc[15];
        float pri = relPri[((tt * R_ + r) * T_ + st) * H_ + h];
        sc *= pri * 0.25f;
        if (valid) {
            g_score[(size_t)p * H_ + h] = sc;        // coalesced: permuted index
            atomicMax(&g_mx[t * H_ + h], fmap(sc));
        }
    }
}

__global__ void k_edgeB() {
    int idx = blockIdx.x * blockDim.x + threadIdx.x;
    if (idx >= E_ * H_) return;
    int p = idx >> 3, h = idx & 7;
    int t = g_eT[p];
    float m = funmap(g_mx[t * H_ + h]);
    float ex = expf(g_score[idx] - m);
    g_score[idx] = ex;
    atomicAdd(&g_den[t * H_ + h], ex);
}

__global__ void __launch_bounds__(256) k_edgeC(const float* __restrict__ relMsg, int layer) {
    int r = blockIdx.y;
    __shared__ float sA[H_ * 260];
    const float* Ar = relMsg + r * H_ * 256;
    for (int i = threadIdx.x; i < H_ * 256; i += blockDim.x)
        sA[(i >> 8) * 260 + (i & 255)] = Ar[i];
    __syncthreads();

    int lo = g_rOff[r], hi = g_rOff[r + 1];
    int lane = threadIdx.x & 31;
    int h = lane & 7, esub = lane >> 3;
    int warp = blockIdx.x * (blockDim.x >> 5) + (threadIdx.x >> 5);
    int nwarp = gridDim.x * (blockDim.x >> 5);
    const float* A = sA + h * 260;
    const float* tab = g_tabV[layer];

    for (int eb = lo + warp * 4; eb < hi; eb += nwarp * 4) {
        int p = eb + esub;
        bool valid = p < hi;
        if (!valid) p = lo;
        int s = g_eS[p], t = g_eT[p], meta = g_eMeta[p];
        int st = meta & 3, tm = meta >> 4;

        const float* vp = g_Vn + (size_t)s * D_ + h * 16;
        const float* tp = tab + (size_t)(st * ML_ + tm) * 128 + h * 16;
        float vr[16];
        #pragma unroll
        for (int q4 = 0; q4 < 4; q4++) {
            float4 a = *(const float4*)(vp + q4 * 4);
            float4 b = *(const float4*)(tp + q4 * 4);
            vr[q4 * 4 + 0] = a.x + b.x; vr[q4 * 4 + 1] = a.y + b.y;
            vr[q4 * 4 + 2] = a.z + b.z; vr[q4 * 4 + 3] = a.w + b.w;
        }
        float acc[16];
        #pragma unroll
        for (int j = 0; j < 16; j++) acc[j] = 0.f;
        #pragma unroll
        for (int kk = 0; kk < 16; kk++) {
            float kv = vr[kk];
            const float4* ap = (const float4*)(A + kk * 16);
            float4 a0 = ap[0], a1 = ap[1], a2 = ap[2], a3 = ap[3];
            acc[0]  += kv * a0.x; acc[1]  += kv * a0.y; acc[2]  += kv * a0.z; acc[3]  += kv * a0.w;
            acc[4]  += kv * a1.x; acc[5]  += kv * a1.y; acc[6]  += kv * a1.z; acc[7]  += kv * a1.w;
            acc[8]  += kv * a2.x; acc[9]  += kv * a2.y; acc[10] += kv * a2.z; acc[11] += kv * a2.w;
            acc[12] += kv * a3.x; acc[13] += kv * a3.y; acc[14] += kv * a3.z; acc[15] += kv * a3.w;
        }
        float ex = g_score[(size_t)p * H_ + h];
        float den = g_den[t * H_ + h];
        float att = ex / den;
        if (valid) {
            float* op = g_aggr + (size_t)t * D_ + h * 16;
            red_add_v4(op,      acc[0] * att,  acc[1] * att,  acc[2] * att,  acc[3] * att);
            red_add_v4(op + 4,  acc[4] * att,  acc[5] * att,  acc[6] * att,  acc[7] * att);
            red_add_v4(op + 8,  acc[8] * att,  acc[9] * att,  acc[10] * att, acc[11] * att);
            red_add_v4(op + 12, acc[12] * att, acc[13] * att, acc[14] * att, acc[15] * att);
        }
    }
}

// ---------------- launch ----------------
static cudaStream_t s_side = nullptr;
static cudaEvent_t evF = nullptr, evS = nullptr, evT = nullptr, evU = nullptr;

extern "C" void kernel_launch(void* const* d_in, const int* in_sizes, int n_in,
                              void* d_out, int out_size) {
    const float* node_feature = (const float*)d_in[0];
    const int*   node_type    = (const int*)d_in[1];
    const int*   edge_index   = (const int*)d_in[2];
    const int*   edge_type    = (const int*)d_in[3];
    const int*   edge_time    = (const int*)d_in[4];
    const float* adapt_w      = (const float*)d_in[5];
    const float* adapt_b      = (const float*)d_in[6];
    const float* Wk           = (const float*)d_in[7];
    const float* bk           = (const float*)d_in[8];
    const float* Wq           = (const float*)d_in[9];
    const float* bq           = (const float*)d_in[10];
    const float* Wv           = (const float*)d_in[11];
    const float* bv           = (const float*)d_in[12];
    const float* Wa           = (const float*)d_in[13];
    const float* ba           = (const float*)d_in[14];
    const float* rel_pri      = (const float*)d_in[15];
    const float* rel_att      = (const float*)d_in[16];
    const float* rel_msg      = (const float*)d_in[17];
    const float* skip         = (const float*)d_in[18];
    const float* rte_w        = (const float*)d_in[19];
    const float* rte_b        = (const float*)d_in[20];

    const int* src = edge_index;
    const int* tgt = edge_index + E_;

    if (!s_side) {
        cudaStreamCreateWithFlags(&s_side, cudaStreamNonBlocking);
        cudaEventCreateWithFlags(&evF, cudaEventDisableTiming);
        cudaEventCreateWithFlags(&evS, cudaEventDisableTiming);
        cudaEventCreateWithFlags(&evT, cudaEventDisableTiming);
        cudaEventCreateWithFlags(&evU, cudaEventDisableTiming);
        cudaFuncSetAttribute(k_typed_gemm, cudaFuncAttributeMaxDynamicSharedMemorySize, GEMM_SMEM);
        cudaFuncSetAttribute(k_qkv_gemm, cudaFuncAttributeMaxDynamicSharedMemorySize, GEMM_SMEM);
    }

    float *px, *pq, *pk, *pv, *pa;
    cudaGetSymbolAddress((void**)&px, g_x);
    cudaGetSymbolAddress((void**)&pq, g_Qn);
    cudaGetSymbolAddress((void**)&pk, g_Kn);
    cudaGetSymbolAddress((void**)&pv, g_Vn);
    cudaGetSymbolAddress((void**)&pa, g_aggr);

    dim3 ggrid((N_ + 127) / 128, T_);
    dim3 egrid(128, R_);
    const int WSPLIT_GRID = (T_ * D_ * D_ + 255) / 256;

    // ---- fork: side stream does all edge/table/weight prep ----
    cudaEventRecord(evF, 0);
    cudaStreamWaitEvent(s_side, evF, 0);

    k_init_once<<<1, 32, 0, s_side>>>();
    k_count_r<<<(E_ + 255) / 256, 256, 0, s_side>>>(edge_type);
    k_scan_r<<<1, 1, 0, s_side>>>();
    k_scatter_r<<<(E_ + 255) / 256, 256, 0, s_side>>>(src, tgt, edge_type, edge_time, node_type);
    k_rte_tab<<<ML_, 128, 0, s_side>>>();
    for (int l = 0; l < 2; l++) {
        size_t woff = (size_t)l * T_ * 128 * 128;
        k_rte_proj<<<ML_, 128, 0, s_side>>>(rte_w + (size_t)l * 256 * 128, rte_b + (size_t)l * 128);
        k_tables<<<T_ * ML_, 128, 0, s_side>>>(Wk + woff, Wv + woff, l);
        k_wsplit<<<WSPLIT_GRID, 256, 0, s_side>>>(Wq + woff, 1 + 4 * l);
        k_wsplit<<<WSPLIT_GRID, 256, 0, s_side>>>(Wk + woff, 2 + 4 * l);
        k_wsplit<<<WSPLIT_GRID, 256, 0, s_side>>>(Wv + woff, 3 + 4 * l);
        k_wsplit<<<WSPLIT_GRID, 256, 0, s_side>>>(Wa + woff, 4 + 4 * l);
    }
    k_init_layer<<<2048, 256, 0, s_side>>>();
    cudaEventRecord(evS, s_side);

    // ---- main: type buckets + adapt GEMM (overlaps side prep) ----
    k_build_type<<<(N_ + 255) / 256, 256>>>(node_type);
    k_wsplit<<<WSPLIT_GRID, 256>>>(adapt_w, 0);
    k_typed_gemm<<<ggrid, 256, GEMM_SMEM>>>(0, 1, node_feature, 0, adapt_b, px, px, nullptr);

    cudaStreamWaitEvent(0, evS, 0);   // join side prep

    for (int l = 0; l < 2; l++) {
        size_t boff = (size_t)l * T_ * 128;

        k_qkv_gemm<<<ggrid, 256, GEMM_SMEM>>>(px, 1 + 4 * l,
                                              bq + boff, bk + boff, bv + boff,
                                              pq, pk, pv);
        if (l == 1) cudaStreamWaitEvent(0, evU, 0);   // init_layer(l1) done

        k_edgeA<<<egrid, 256>>>(rel_att + (size_t)l * R_ * H_ * 256,
                                rel_pri + (size_t)l * T_ * R_ * T_ * H_, l);
        k_edgeB<<<(E_ * H_ + 255) / 256, 256>>>();
        k_edgeC<<<egrid, 256>>>(rel_msg + (size_t)l * R_ * H_ * 256, l);

        // x = alpha * typed_linear(gelu(aggr); Wa) + (1-alpha) * x
        float* outp = (l == 1) ? (float*)d_out : px;
        k_typed_gemm<<<ggrid, 256, GEMM_SMEM>>>(1, 2, pa, 4 + 4 * l, ba + boff,
                                                outp, px, skip + (size_t)l * T_);

        if (l == 0) {
            // re-init mx/den/aggr for layer 1, overlapped with QKV(l1)
            cudaEventRecord(evT, 0);
            cudaStreamWaitEvent(s_side, evT, 0);
            k_init_layer<<<2048, 256, 0, s_side>>>();
            cudaEventRecord(evU, s_side);
        }
    }
}

// round 5
// speedup vs baseline: 1.4155x; 1.1386x over previous
#include <cuda_runtime.h>
#include <cuda_bf16.h>
#include <math.h>

#define N_ 100000
#define E_ 500000
#define D_ 128
#define T_ 3
#define R_ 4
#define H_ 8
#define ML_ 240
#define TD_ ((size_t)N_*(size_t)D_)
#define PAD_ 136                        // bf16 elems per smem row (272B stride)
#define GEMM_SMEM (4 * 128 * PAD_ * 2)  // Ahi, Alo, Whi, Wlo
#define REL_SMEM  (2 * 128 * PAD_ * 2)  // Ahi, Alo only
#define NMAT_ 9                         // adapt + (q,k,v,a) x 2 layers
#define BDPAD_ 24
#define BDSZ_ (H_*16*BDPAD_)            // 3072 bf16 per (l,w,r) matrix

__device__ float g_x[TD_];
__device__ float g_Qn[TD_];
__device__ float g_Kn[TD_];
__device__ float g_Vn[TD_];
__device__ float g_aggr[TD_];
__device__ float g_Kr[(size_t)R_*N_*D_];       // 205 MB
__device__ float g_Vr[(size_t)R_*N_*D_];       // 205 MB
__device__ float g_score[(size_t)E_*H_];
__device__ int   g_mx[N_*H_];
__device__ float g_den[N_*H_];
__device__ float g_rte_tab[ML_*2*D_];
__device__ float g_rte_proj[ML_*D_];
__device__ float g_tabKr[2][(size_t)R_*T_*ML_*D_];
__device__ float g_tabVr[2][(size_t)R_*T_*ML_*D_];
__device__ __nv_bfloat16 g_Wh[(size_t)NMAT_*T_*D_*D_];
__device__ __nv_bfloat16 g_Wl[(size_t)NMAT_*T_*D_*D_];
__device__ __nv_bfloat16 g_BDh[2*2*R_*BDSZ_];  // [layer][att/msg][r][h][k][c pad24]
__device__ __nv_bfloat16 g_BDl[2*2*R_*BDSZ_];
__device__ int   g_typeList[T_][N_];
__device__ int   g_typeCnt[T_];
__device__ int   g_rCnt[R_];
__device__ int   g_rOff[R_+1];
__device__ int   g_rFill[R_];
__device__ int   g_eS[E_];
__device__ int   g_eT[E_];
__device__ int   g_eMeta[E_];   // st | tt<<2 | time<<4

__device__ __forceinline__ int fmap(float f) {
    int i = __float_as_int(f);
    return i >= 0 ? i : (i ^ 0x7fffffff);
}
__device__ __forceinline__ float funmap(int i) {
    return __int_as_float(i >= 0 ? i : (i ^ 0x7fffffff));
}
__device__ __forceinline__ float gelu_f(float x) { return x * normcdff(x); }

__device__ __forceinline__ void red_add_v4(float* p, float a, float b, float c, float d) {
    asm volatile("red.global.add.v4.f32 [%0], {%1,%2,%3,%4};"
                 :: "l"(p), "f"(a), "f"(b), "f"(c), "f"(d) : "memory");
}

// ---------------- mma helpers ----------------
__device__ __forceinline__ void ldsm4(unsigned& r0, unsigned& r1, unsigned& r2, unsigned& r3,
                                      unsigned addr) {
    asm volatile("ldmatrix.sync.aligned.m8n8.x4.shared.b16 {%0,%1,%2,%3}, [%4];"
                 : "=r"(r0), "=r"(r1), "=r"(r2), "=r"(r3) : "r"(addr));
}
__device__ __forceinline__ void ldsm4t(unsigned& r0, unsigned& r1, unsigned& r2, unsigned& r3,
                                       unsigned addr) {
    asm volatile("ldmatrix.sync.aligned.m8n8.x4.trans.shared.b16 {%0,%1,%2,%3}, [%4];"
                 : "=r"(r0), "=r"(r1), "=r"(r2), "=r"(r3) : "r"(addr));
}
__device__ __forceinline__ void mma16816(float* d, const unsigned* a, const unsigned* b) {
    asm volatile("mma.sync.aligned.m16n8k16.row.col.f32.bf16.bf16.f32 "
                 "{%0,%1,%2,%3}, {%4,%5,%6,%7}, {%8,%9}, {%0,%1,%2,%3};"
                 : "+f"(d[0]), "+f"(d[1]), "+f"(d[2]), "+f"(d[3])
                 : "r"(a[0]), "r"(a[1]), "r"(a[2]), "r"(a[3]), "r"(b[0]), "r"(b[1]));
}
__device__ __forceinline__ unsigned pack_bf2(__nv_bfloat16 a, __nv_bfloat16 b) {
    __nv_bfloat162 p(a, b);
    return *reinterpret_cast<unsigned*>(&p);
}

// ---------------- precompute kernels ----------------
__global__ void k_rte_tab() {
    int pos = blockIdx.x;
    int i   = threadIdx.x;
    const float s = 0.08838834764831845f;
    float div;
    if (i >= 5) div = 0.f;   // fp32 10000^ar overflow -> inf -> 0
    else {
        float pf = (float)pow(10000.0, (double)(2 * i));
        div = 1.0f / ((pf / 128.0f) / 2.0f);
    }
    float ang = (float)pos * div;
    double a = (double)ang;
    g_rte_tab[pos * 256 + 2 * i]     = (float)sin(a) * s;
    g_rte_tab[pos * 256 + 2 * i + 1] = (float)cos(a) * s;
}

__global__ void k_rte_proj(const float* __restrict__ w, const float* __restrict__ b) {
    int time = blockIdx.x;
    int d    = threadIdx.x;
    float acc = b[d];
    const float* tr = g_rte_tab + time * 256;
    for (int c = 0; c < 256; c++) acc += tr[c] * w[c * 128 + d];
    g_rte_proj[time * 128 + d] = acc;
}

// per-(type,time) table, then apply rel_att/rel_msg per relation
__global__ void k_tables(const float* __restrict__ Wk, const float* __restrict__ Wv,
                         const float* __restrict__ relAtt, const float* __restrict__ relMsg,
                         int l) {
    __shared__ float sK[128], sV[128];
    int id = blockIdx.x;
    int d  = threadIdx.x;
    int t = id / ML_, time = id % ML_;
    const float* pr = g_rte_proj + time * 128;
    const float* wk = Wk + (size_t)t * 128 * 128;
    const float* wv = Wv + (size_t)t * 128 * 128;
    float aK = 0.f, aV = 0.f;
    for (int k = 0; k < 128; k++) {
        float p = pr[k];
        aK += p * wk[k * 128 + d];
        aV += p * wv[k * 128 + d];
    }
    sK[d] = aK; sV[d] = aV;
    __syncthreads();
    int h = d >> 4, dk = d & 15;
    size_t rowoff = (size_t)(t * ML_ + time) * 128 + d;
    for (int r = 0; r < R_; r++) {
        const float* A = relAtt + ((size_t)r * H_ + h) * 256;
        const float* M = relMsg + ((size_t)r * H_ + h) * 256;
        float k2 = 0.f, v2 = 0.f;
        #pragma unroll
        for (int j = 0; j < 16; j++) {
            k2 += sK[h * 16 + j] * A[j * 16 + dk];
            v2 += sV[h * 16 + j] * M[j * 16 + dk];
        }
        g_tabKr[l][(size_t)r * T_ * ML_ * D_ + rowoff] = k2;
        g_tabVr[l][(size_t)r * T_ * ML_ * D_ + rowoff] = v2;
    }
}

// split a typed weight tensor (T x 128 x 128 fp32) into bf16 hi/lo at slot midx
__global__ void k_wsplit(const float* __restrict__ src, int midx) {
    int i = blockIdx.x * blockDim.x + threadIdx.x;
    int n = T_ * D_ * D_;
    if (i >= n) return;
    size_t off = (size_t)midx * n + i;
    float v = src[i];
    __nv_bfloat16 h = __float2bfloat16_rn(v);
    g_Wh[off] = h;
    g_Wl[off] = __float2bfloat16_rn(v - __bfloat162float(h));
}

// split rel_att/rel_msg (both layers) into padded bf16 hi/lo blockdiag buffers
__global__ void k_relsplit(const float* __restrict__ relAtt, const float* __restrict__ relMsg) {
    int idx = blockIdx.x * blockDim.x + threadIdx.x;
    if (idx >= 2 * 2 * R_ * H_ * 256) return;
    int c = idx & 15, k = (idx >> 4) & 15, h = (idx >> 8) & 7;
    int r = (idx >> 11) & 3, w = (idx >> 13) & 1, l = idx >> 14;
    const float* src = w ? relMsg : relAtt;
    float v = src[(((size_t)l * R_ + r) * H_ + h) * 256 + k * 16 + c];
    __nv_bfloat16 hi = __float2bfloat16_rn(v);
    size_t dst = (size_t)(((l * 2 + w) * R_ + r)) * BDSZ_ + (h * 16 + k) * BDPAD_ + c;
    g_BDh[dst] = hi;
    g_BDl[dst] = __float2bfloat16_rn(v - __bfloat162float(hi));
}

// ---------------- bucketing (block-aggregated atomics) ----------------
__global__ void k_init_once() {
    int i = threadIdx.x;
    if (i < T_) g_typeCnt[i] = 0;
    if (i < R_) { g_rCnt[i] = 0; g_rFill[i] = 0; }
}

__global__ void k_build_type(const int* __restrict__ nt) {
    __shared__ int c[T_];
    __shared__ int base[T_];
    int tid = threadIdx.x;
    if (tid < T_) c[tid] = 0;
    __syncthreads();
    int i = blockIdx.x * blockDim.x + tid;
    int t = -1, rank = 0;
    if (i < N_) { t = nt[i]; rank = atomicAdd(&c[t], 1); }
    __syncthreads();
    if (tid < T_) base[tid] = c[tid] ? atomicAdd(&g_typeCnt[tid], c[tid]) : 0;
    __syncthreads();
    if (i < N_) g_typeList[t][base[t] + rank] = i;
}

__global__ void k_count_r(const int* __restrict__ et) {
    __shared__ int c[R_];
    int tid = threadIdx.x;
    if (tid < R_) c[tid] = 0;
    __syncthreads();
    int i = blockIdx.x * blockDim.x + tid;
    if (i < E_) atomicAdd(&c[et[i]], 1);
    __syncthreads();
    if (tid < R_ && c[tid]) atomicAdd(&g_rCnt[tid], c[tid]);
}

__global__ void k_scan_r() {
    g_rOff[0] = 0;
    for (int r = 0; r < R_; r++) g_rOff[r + 1] = g_rOff[r] + g_rCnt[r];
}

__global__ void k_scatter_r(const int* __restrict__ src, const int* __restrict__ tgt,
                            const int* __restrict__ et, const int* __restrict__ etm,
                            const int* __restrict__ nt) {
    __shared__ int c[R_];
    __shared__ int base[R_];
    int tid = threadIdx.x;
    if (tid < R_) c[tid] = 0;
    __syncthreads();
    int e = blockIdx.x * blockDim.x + tid;
    int r = -1, rank = 0;
    if (e < E_) { r = et[e]; rank = atomicAdd(&c[r], 1); }
    __syncthreads();
    if (tid < R_) base[tid] = c[tid] ? atomicAdd(&g_rFill[tid], c[tid]) : 0;
    __syncthreads();
    if (e < E_) {
        int p = g_rOff[r] + base[r] + rank;
        int s = src[e], t = tgt[e];
        g_eS[p] = s;
        g_eT[p] = t;
        g_eMeta[p] = nt[s] | (nt[t] << 2) | (etm[e] << 4);
    }
}

__global__ void k_init_layer() {
    int stride = gridDim.x * blockDim.x;
    int i0 = blockIdx.x * blockDim.x + threadIdx.x;
    for (int i = i0; i < N_ * H_; i += stride) { g_mx[i] = 0x807FFFFF; g_den[i] = 0.f; }
    for (size_t i = i0; i < TD_; i += (size_t)stride) g_aggr[i] = 0.f;
}

// ---------------- GEMM building blocks ----------------
__device__ __forceinline__ void load_w_smem(__nv_bfloat16* sWh, __nv_bfloat16* sWl,
                                            int midx, int t, int tid) {
    size_t base = ((size_t)midx * T_ + t) * D_ * D_;
    const uint4* wh4 = (const uint4*)(g_Wh + base);
    const uint4* wl4 = (const uint4*)(g_Wl + base);
    #pragma unroll
    for (int it = 0; it < 8; it++) {
        int idx = it * 256 + tid;
        int row = idx >> 4;
        int col = (idx & 15) * 8;
        *(uint4*)(sWh + row * PAD_ + col) = wh4[idx];
        *(uint4*)(sWl + row * PAD_ + col) = wl4[idx];
    }
}

__device__ __forceinline__ void cvt_store(__nv_bfloat16* sAh, __nv_bfloat16* sAl,
                                          int row, int col, float4 v) {
    __nv_bfloat16 h0 = __float2bfloat16_rn(v.x), h1 = __float2bfloat16_rn(v.y);
    __nv_bfloat16 h2 = __float2bfloat16_rn(v.z), h3 = __float2bfloat16_rn(v.w);
    __nv_bfloat16 l0 = __float2bfloat16_rn(v.x - __bfloat162float(h0));
    __nv_bfloat16 l1 = __float2bfloat16_rn(v.y - __bfloat162float(h1));
    __nv_bfloat16 l2 = __float2bfloat16_rn(v.z - __bfloat162float(h2));
    __nv_bfloat16 l3 = __float2bfloat16_rn(v.w - __bfloat162float(h3));
    *(uint2*)(sAh + row * PAD_ + col) = make_uint2(pack_bf2(h0, h1), pack_bf2(h2, h3));
    *(uint2*)(sAl + row * PAD_ + col) = make_uint2(pack_bf2(l0, l1), pack_bf2(l2, l3));
}

__device__ __forceinline__ void load_a_smem(__nv_bfloat16* sAh, __nv_bfloat16* sAl,
                                            const float* __restrict__ in,
                                            const int* sList, int inop, int tid) {
    #pragma unroll
    for (int it = 0; it < 16; it++) {
        int idx = it * 256 + tid;
        int row = idx >> 5;
        int col = (idx & 31) << 2;
        int grow = sList[row];
        float4 v = *(const float4*)(in + (size_t)grow * D_ + col);
        if (inop == 1) {
            v.x = gelu_f(v.x); v.y = gelu_f(v.y); v.z = gelu_f(v.z); v.w = gelu_f(v.w);
        }
        cvt_store(sAh, sAl, row, col, v);
    }
}

__device__ __forceinline__ void mma_tile(float (&acc)[2][8][4],
                                         const __nv_bfloat16* sAh, const __nv_bfloat16* sAl,
                                         const __nv_bfloat16* sWh, const __nv_bfloat16* sWl,
                                         int mbase, int nbase, int lane) {
    int aRow = mbase + (lane & 15);
    int aColAdd = (lane >> 4) << 3;
    int bg = lane >> 3;
    int bRowAdd = ((bg & 1) << 3) + (lane & 7);
    int bColAdd = (bg >> 1) << 3;

    unsigned aHbase = (unsigned)__cvta_generic_to_shared(sAh + aRow * PAD_);
    unsigned aLbase = (unsigned)__cvta_generic_to_shared(sAl + aRow * PAD_);
    unsigned wHbase = (unsigned)__cvta_generic_to_shared(sWh);
    unsigned wLbase = (unsigned)__cvta_generic_to_shared(sWl);

    #pragma unroll
    for (int kc = 0; kc < 8; kc++) {
        int k0 = kc * 16;
        unsigned ah[2][4], al[2][4];
        #pragma unroll
        for (int mt = 0; mt < 2; mt++) {
            unsigned off = (mt * 16 * PAD_ + k0 + aColAdd) * 2;
            ldsm4(ah[mt][0], ah[mt][1], ah[mt][2], ah[mt][3], aHbase + off);
            ldsm4(al[mt][0], al[mt][1], al[mt][2], al[mt][3], aLbase + off);
        }
        #pragma unroll
        for (int nt2 = 0; nt2 < 4; nt2++) {
            int nb = nbase + nt2 * 16;
            unsigned off = ((k0 + bRowAdd) * PAD_ + nb + bColAdd) * 2;
            unsigned bh[4], bl[4];
            ldsm4t(bh[0], bh[1], bh[2], bh[3], wHbase + off);
            ldsm4t(bl[0], bl[1], bl[2], bl[3], wLbase + off);
            #pragma unroll
            for (int mt = 0; mt < 2; mt++) {
                mma16816(acc[mt][nt2 * 2],     ah[mt], bh);
                mma16816(acc[mt][nt2 * 2],     al[mt], bh);
                mma16816(acc[mt][nt2 * 2],     ah[mt], bl);
                mma16816(acc[mt][nt2 * 2 + 1], ah[mt], bh + 2);
                mma16816(acc[mt][nt2 * 2 + 1], al[mt], bh + 2);
                mma16816(acc[mt][nt2 * 2 + 1], ah[mt], bl + 2);
            }
        }
    }
}

__device__ __forceinline__ void epi_bias(float (&acc)[2][8][4], const float* Bt,
                                         float* out, const int* sList, int rem,
                                         int mbase, int nbase, int lane) {
    int rq = lane >> 2, cq = (lane & 3) * 2;
    #pragma unroll
    for (int mt = 0; mt < 2; mt++) {
        int rl0 = mbase + mt * 16 + rq;
        #pragma unroll
        for (int nt = 0; nt < 8; nt++) {
            int col = nbase + nt * 8 + cq;
            float b0 = Bt[col], b1 = Bt[col + 1];
            float* a = acc[mt][nt];
            #pragma unroll
            for (int half = 0; half < 2; half++) {
                int rl = rl0 + half * 8;
                if (rl < rem) {
                    int grow = sList[rl];
                    float* op = out + (size_t)grow * D_ + col;
                    *(float2*)op = make_float2(a[half * 2] + b0, a[half * 2 + 1] + b1);
                }
            }
        }
    }
}

// ---------------- fused QKV GEMM ----------------
__global__ void __launch_bounds__(256) k_qkv_gemm(
    const float* __restrict__ in, int midx0,
    const float* __restrict__ Bq, const float* __restrict__ Bk, const float* __restrict__ Bv,
    float* __restrict__ Oq, float* __restrict__ Ok, float* __restrict__ Ov)
{
    int t = blockIdx.y;
    int cnt = g_typeCnt[t];
    int base = blockIdx.x * 128;
    if (base >= cnt) return;
    const int* list = &g_typeList[t][base];
    int rem = cnt - base; if (rem > 128) rem = 128;

    extern __shared__ __nv_bfloat16 sm[];
    __nv_bfloat16* sAh = sm;
    __nv_bfloat16* sAl = sAh + 128 * PAD_;
    __nv_bfloat16* sWh = sAl + 128 * PAD_;
    __nv_bfloat16* sWl = sWh + 128 * PAD_;
    __shared__ int sList[128];

    int tid = threadIdx.x;
    if (tid < 128) sList[tid] = (tid < rem) ? list[tid] : list[0];
    __syncthreads();

    load_a_smem(sAh, sAl, in, sList, 0, tid);

    int warp = tid >> 5, lane = tid & 31;
    int mbase = (warp & 3) * 32;
    int nbase = (warp >> 2) * 64;

    #pragma unroll
    for (int s = 0; s < 3; s++) {
        if (s > 0) __syncthreads();
        load_w_smem(sWh, sWl, midx0 + s, t, tid);
        __syncthreads();

        float acc[2][8][4];
        #pragma unroll
        for (int i = 0; i < 2; i++)
            #pragma unroll
            for (int j = 0; j < 8; j++)
                #pragma unroll
                for (int q = 0; q < 4; q++) acc[i][j][q] = 0.f;

        mma_tile(acc, sAh, sAl, sWh, sWl, mbase, nbase, lane);

        const float* Bt = (s == 0 ? Bq : s == 1 ? Bk : Bv) + t * D_;
        float* out = (s == 0 ? Oq : s == 1 ? Ok : Ov);
        epi_bias(acc, Bt, out, sList, rem, mbase, nbase, lane);
    }
}

// ---------------- single typed GEMM (adapt / trans) ----------------
__global__ void __launch_bounds__(256) k_typed_gemm(
    int inop, int outop,
    const float* __restrict__ in, int midx,
    const float* __restrict__ Bbase,
    float* __restrict__ out,
    const float* __restrict__ prev,
    const float* __restrict__ skipv)
{
    int t = blockIdx.y;
    int cnt = g_typeCnt[t];
    int base = blockIdx.x * 128;
    if (base >= cnt) return;
    const int* list = &g_typeList[t][base];
    int rem = cnt - base; if (rem > 128) rem = 128;

    extern __shared__ __nv_bfloat16 sm[];
    __nv_bfloat16* sAh = sm;
    __nv_bfloat16* sAl = sAh + 128 * PAD_;
    __nv_bfloat16* sWh = sAl + 128 * PAD_;
    __nv_bfloat16* sWl = sWh + 128 * PAD_;
    __shared__ int sList[128];

    int tid = threadIdx.x;
    if (tid < 128) sList[tid] = (tid < rem) ? list[tid] : list[0];
    __syncthreads();

    load_a_smem(sAh, sAl, in, sList, inop, tid);
    load_w_smem(sWh, sWl, midx, t, tid);
    __syncthreads();

    int warp = tid >> 5, lane = tid & 31;
    int mbase = (warp & 3) * 32;
    int nbase = (warp >> 2) * 64;

    float acc[2][8][4];
    #pragma unroll
    for (int i = 0; i < 2; i++)
        #pragma unroll
        for (int j = 0; j < 8; j++)
            #pragma unroll
            for (int q = 0; q < 4; q++) acc[i][j][q] = 0.f;

    mma_tile(acc, sAh, sAl, sWh, sWl, mbase, nbase, lane);

    const float* Bt = Bbase + t * D_;
    float alpha = 0.f, beta = 0.f;
    if (outop == 2) { alpha = 1.f / (1.f + expf(-skipv[t])); beta = 1.f - alpha; }

    int rq = lane >> 2, cq = (lane & 3) * 2;
    #pragma unroll
    for (int mt = 0; mt < 2; mt++) {
        int rl0 = mbase + mt * 16 + rq;
        #pragma unroll
        for (int nt = 0; nt < 8; nt++) {
            int col = nbase + nt * 8 + cq;
            float b0 = Bt[col], b1 = Bt[col + 1];
            float* a = acc[mt][nt];
            #pragma unroll
            for (int half = 0; half < 2; half++) {
                int rl = rl0 + half * 8;
                if (rl < rem) {
                    int grow = sList[rl];
                    float v0 = a[half * 2]     + b0;
                    float v1 = a[half * 2 + 1] + b1;
                    if (outop == 1) { v0 = tanhf(v0); v1 = tanhf(v1); }
                    else {
                        const float* pp = prev + (size_t)grow * D_ + col;
                        float2 old = *(const float2*)pp;
                        v0 = alpha * v0 + beta * old.x;
                        v1 = alpha * v1 + beta * old.y;
                    }
                    *(float2*)(out + (size_t)grow * D_ + col) = make_float2(v0, v1);
                }
            }
        }
    }
}

// ---------------- block-diagonal relation GEMM: out[r][n] = in[n] . BD_r ----------------
__global__ void __launch_bounds__(256) k_rel_gemm(
    const float* __restrict__ in,
    const __nv_bfloat16* __restrict__ BDh, const __nv_bfloat16* __restrict__ BDl,
    float* __restrict__ out)
{
    int r = blockIdx.y;
    int base = blockIdx.x * 128;
    int rem = N_ - base; if (rem > 128) rem = 128;

    extern __shared__ __nv_bfloat16 sm[];
    __nv_bfloat16* sAh = sm;
    __nv_bfloat16* sAl = sAh + 128 * PAD_;
    __shared__ __nv_bfloat16 sBh[BDSZ_], sBl[BDSZ_];

    int tid = threadIdx.x;
    {
        const uint4* srcH = (const uint4*)(BDh + (size_t)r * BDSZ_);
        const uint4* srcL = (const uint4*)(BDl + (size_t)r * BDSZ_);
        uint4* dh = (uint4*)sBh;
        uint4* dl = (uint4*)sBl;
        for (int i = tid; i < BDSZ_ / 8; i += 256) { dh[i] = srcH[i]; dl[i] = srcL[i]; }
    }
    #pragma unroll
    for (int it = 0; it < 16; it++) {
        int idx = it * 256 + tid;
        int row = idx >> 5;
        int col = (idx & 31) << 2;
        int grow = base + (row < rem ? row : 0);
        float4 v = *(const float4*)(in + (size_t)grow * D_ + col);
        cvt_store(sAh, sAl, row, col, v);
    }
    __syncthreads();

    int warp = tid >> 5, lane = tid & 31;
    int mbase = (warp & 3) * 32;
    int nbase = (warp >> 2) * 64;

    float acc[2][8][4];
    #pragma unroll
    for (int i = 0; i < 2; i++)
        #pragma unroll
        for (int j = 0; j < 8; j++)
            #pragma unroll
            for (int q = 0; q < 4; q++) acc[i][j][q] = 0.f;

    int aColAdd = (lane >> 4) << 3;
    int bg = lane >> 3;
    int bRowAdd = ((bg & 1) << 3) + (lane & 7);
    int bColAdd = (bg >> 1) << 3;
    unsigned aHbase = (unsigned)__cvta_generic_to_shared(sAh + (mbase + (lane & 15)) * PAD_);
    unsigned aLbase = (unsigned)__cvta_generic_to_shared(sAl + (mbase + (lane & 15)) * PAD_);
    unsigned bHbase = (unsigned)__cvta_generic_to_shared(sBh);
    unsigned bLbase = (unsigned)__cvta_generic_to_shared(sBl);

    #pragma unroll
    for (int nt2 = 0; nt2 < 4; nt2++) {
        int head = (nbase >> 4) + nt2;                     // diagonal block only
        unsigned ah[2][4], al[2][4];
        #pragma unroll
        for (int mt = 0; mt < 2; mt++) {
            unsigned offA = (mt * 16 * PAD_ + head * 16 + aColAdd) * 2;
            ldsm4(ah[mt][0], ah[mt][1], ah[mt][2], ah[mt][3], aHbase + offA);
            ldsm4(al[mt][0], al[mt][1], al[mt][2], al[mt][3], aLbase + offA);
        }
        unsigned offB = ((head * 16 + bRowAdd) * BDPAD_ + bColAdd) * 2;
        unsigned bh[4], bl[4];
        ldsm4t(bh[0], bh[1], bh[2], bh[3], bHbase + offB);
        ldsm4t(bl[0], bl[1], bl[2], bl[3], bLbase + offB);
        #pragma unroll
        for (int mt = 0; mt < 2; mt++) {
            mma16816(acc[mt][nt2 * 2],     ah[mt], bh);
            mma16816(acc[mt][nt2 * 2],     al[mt], bh);
            mma16816(acc[mt][nt2 * 2],     ah[mt], bl);
            mma16816(acc[mt][nt2 * 2 + 1], ah[mt], bh + 2);
            mma16816(acc[mt][nt2 * 2 + 1], al[mt], bh + 2);
            mma16816(acc[mt][nt2 * 2 + 1], ah[mt], bl + 2);
        }
    }

    float* outR = out + (size_t)r * N_ * D_;
    int rq = lane >> 2, cq = (lane & 3) * 2;
    #pragma unroll
    for (int mt = 0; mt < 2; mt++) {
        int rl0 = mbase + mt * 16 + rq;
        #pragma unroll
        for (int nt = 0; nt < 8; nt++) {
            int col = nbase + nt * 8 + cq;
            float* a = acc[mt][nt];
            #pragma unroll
            for (int half = 0; half < 2; half++) {
                int rl = rl0 + half * 8;
                if (rl < rem)
                    *(float2*)(outR + (size_t)(base + rl) * D_ + col) =
                        make_float2(a[half * 2], a[half * 2 + 1]);
            }
        }
    }
}

// ---------------- edge pass A: scores + segment max (lightweight) ----------------
__global__ void __launch_bounds__(256) k_edgeA(const float* __restrict__ tabKr,
                                               const float* __restrict__ relPri) {
    int r = blockIdx.y;
    int lo = g_rOff[r], hi = g_rOff[r + 1];
    int lane = threadIdx.x & 31;
    int h = lane & 7, esub = lane >> 3;
    int warp = blockIdx.x * (blockDim.x >> 5) + (threadIdx.x >> 5);
    int nwarp = gridDim.x * (blockDim.x >> 5);
    const float* KrR = g_Kr + (size_t)r * N_ * D_;
    const float* tabR = tabKr + (size_t)r * T_ * ML_ * D_;

    for (int eb = lo + warp * 4; eb < hi; eb += nwarp * 4) {
        int p = eb + esub;
        bool valid = p < hi;
        if (!valid) p = lo;
        int s = g_eS[p], t = g_eT[p], meta = g_eMeta[p];
        int st = meta & 3, tt = (meta >> 2) & 3, tm = meta >> 4;

        const float4* kp = (const float4*)(KrR + (size_t)s * D_ + h * 16);
        const float4* tp = (const float4*)(tabR + (size_t)(st * ML_ + tm) * D_ + h * 16);
        const float4* qp = (const float4*)(g_Qn + (size_t)t * D_ + h * 16);
        float sc = 0.f;
        #pragma unroll
        for (int i = 0; i < 4; i++) {
            float4 k4 = kp[i], t4 = tp[i], q4 = qp[i];
            sc += q4.x * (k4.x + t4.x) + q4.y * (k4.y + t4.y)
                + q4.z * (k4.z + t4.z) + q4.w * (k4.w + t4.w);
        }
        float pri = relPri[((tt * R_ + r) * T_ + st) * H_ + h];
        sc *= pri * 0.25f;
        if (valid) {
            g_score[(size_t)p * H_ + h] = sc;
            atomicMax(&g_mx[t * H_ + h], fmap(sc));
        }
    }
}

__global__ void k_edgeB() {
    int idx = blockIdx.x * blockDim.x + threadIdx.x;
    if (idx >= E_ * H_) return;
    int p = idx >> 3, h = idx & 7;
    int t = g_eT[p];
    float m = funmap(g_mx[t * H_ + h]);
    float ex = expf(g_score[idx] - m);
    g_score[idx] = ex;
    atomicAdd(&g_den[t * H_ + h], ex);
}

// ---------------- edge pass C: weighted message scatter (lightweight) ----------------
__global__ void __launch_bounds__(256) k_edgeC(const float* __restrict__ tabVr) {
    int r = blockIdx.y;
    int lo = g_rOff[r], hi = g_rOff[r + 1];
    int lane = threadIdx.x & 31;
    int h = lane & 7, esub = lane >> 3;
    int warp = blockIdx.x * (blockDim.x >> 5) + (threadIdx.x >> 5);
    int nwarp = gridDim.x * (blockDim.x >> 5);
    const float* VrR = g_Vr + (size_t)r * N_ * D_;
    const float* tabR = tabVr + (size_t)r * T_ * ML_ * D_;

    for (int eb = lo + warp * 4; eb < hi; eb += nwarp * 4) {
        int p = eb + esub;
        bool valid = p < hi;
        if (!valid) p = lo;
        int s = g_eS[p], t = g_eT[p], meta = g_eMeta[p];
        int st = meta & 3, tm = meta >> 4;

        float ex = g_score[(size_t)p * H_ + h];
        float den = g_den[t * H_ + h];
        float att = ex / den;

        const float4* vp = (const float4*)(VrR + (size_t)s * D_ + h * 16);
        const float4* tp = (const float4*)(tabR + (size_t)(st * ML_ + tm) * D_ + h * 16);
        if (valid) {
            float* op = g_aggr + (size_t)t * D_ + h * 16;
            #pragma unroll
            for (int i = 0; i < 4; i++) {
                float4 v4 = vp[i], t4 = tp[i];
                red_add_v4(op + i * 4, (v4.x + t4.x) * att, (v4.y + t4.y) * att,
                                       (v4.z + t4.z) * att, (v4.w + t4.w) * att);
            }
        }
    }
}

// ---------------- launch ----------------
static cudaStream_t s_side = nullptr;
static cudaEvent_t evF = nullptr, evS = nullptr, evT = nullptr, evU = nullptr;
static cudaEvent_t evQ[2] = {nullptr, nullptr}, evV[2] = {nullptr, nullptr};

extern "C" void kernel_launch(void* const* d_in, const int* in_sizes, int n_in,
                              void* d_out, int out_size) {
    const float* node_feature = (const float*)d_in[0];
    const int*   node_type    = (const int*)d_in[1];
    const int*   edge_index   = (const int*)d_in[2];
    const int*   edge_type    = (const int*)d_in[3];
    const int*   edge_time    = (const int*)d_in[4];
    const float* adapt_w      = (const float*)d_in[5];
    const float* adapt_b      = (const float*)d_in[6];
    const float* Wk           = (const float*)d_in[7];
    const float* bk           = (const float*)d_in[8];
    const float* Wq           = (const float*)d_in[9];
    const float* bq           = (const float*)d_in[10];
    const float* Wv           = (const float*)d_in[11];
    const float* bv           = (const float*)d_in[12];
    const float* Wa           = (const float*)d_in[13];
    const float* ba           = (const float*)d_in[14];
    const float* rel_pri      = (const float*)d_in[15];
    const float* rel_att      = (const float*)d_in[16];
    const float* rel_msg      = (const float*)d_in[17];
    const float* skip         = (const float*)d_in[18];
    const float* rte_w        = (const float*)d_in[19];
    const float* rte_b        = (const float*)d_in[20];

    const int* src = edge_index;
    const int* tgt = edge_index + E_;

    if (!s_side) {
        cudaStreamCreateWithFlags(&s_side, cudaStreamNonBlocking);
        cudaEventCreateWithFlags(&evF, cudaEventDisableTiming);
        cudaEventCreateWithFlags(&evS, cudaEventDisableTiming);
        cudaEventCreateWithFlags(&evT, cudaEventDisableTiming);
        cudaEventCreateWithFlags(&evU, cudaEventDisableTiming);
        for (int i = 0; i < 2; i++) {
            cudaEventCreateWithFlags(&evQ[i], cudaEventDisableTiming);
            cudaEventCreateWithFlags(&evV[i], cudaEventDisableTiming);
        }
        cudaFuncSetAttribute(k_typed_gemm, cudaFuncAttributeMaxDynamicSharedMemorySize, GEMM_SMEM);
        cudaFuncSetAttribute(k_qkv_gemm, cudaFuncAttributeMaxDynamicSharedMemorySize, GEMM_SMEM);
        cudaFuncSetAttribute(k_rel_gemm, cudaFuncAttributeMaxDynamicSharedMemorySize, REL_SMEM);
    }

    float *px, *pq, *pk, *pv, *pa, *pKr, *pVr, *ptK0, *ptV0;
    __nv_bfloat16 *pBDh, *pBDl;
    cudaGetSymbolAddress((void**)&px, g_x);
    cudaGetSymbolAddress((void**)&pq, g_Qn);
    cudaGetSymbolAddress((void**)&pk, g_Kn);
    cudaGetSymbolAddress((void**)&pv, g_Vn);
    cudaGetSymbolAddress((void**)&pa, g_aggr);
    cudaGetSymbolAddress((void**)&pKr, g_Kr);
    cudaGetSymbolAddress((void**)&pVr, g_Vr);
    cudaGetSymbolAddress((void**)&ptK0, g_tabKr);
    cudaGetSymbolAddress((void**)&ptV0, g_tabVr);
    cudaGetSymbolAddress((void**)&pBDh, g_BDh);
    cudaGetSymbolAddress((void**)&pBDl, g_BDl);
    const size_t TABSTRIDE = (size_t)R_ * T_ * ML_ * D_;

    dim3 ggrid((N_ + 127) / 128, T_);
    dim3 rgrid((N_ + 127) / 128, R_);
    dim3 egrid(128, R_);
    const int WSPLIT_GRID = (T_ * D_ * D_ + 255) / 256;

    // ---- fork: side stream does all edge/table/weight prep ----
    cudaEventRecord(evF, 0);
    cudaStreamWaitEvent(s_side, evF, 0);

    k_init_once<<<1, 32, 0, s_side>>>();
    k_count_r<<<(E_ + 255) / 256, 256, 0, s_side>>>(edge_type);
    k_scan_r<<<1, 1, 0, s_side>>>();
    k_scatter_r<<<(E_ + 255) / 256, 256, 0, s_side>>>(src, tgt, edge_type, edge_time, node_type);
    k_rte_tab<<<ML_, 128, 0, s_side>>>();
    k_relsplit<<<(2 * 2 * R_ * H_ * 256 + 255) / 256, 256, 0, s_side>>>(rel_att, rel_msg);
    for (int l = 0; l < 2; l++) {
        size_t woff = (size_t)l * T_ * 128 * 128;
        k_rte_proj<<<ML_, 128, 0, s_side>>>(rte_w + (size_t)l * 256 * 128, rte_b + (size_t)l * 128);
        k_tables<<<T_ * ML_, 128, 0, s_side>>>(Wk + woff, Wv + woff,
                                               rel_att + (size_t)l * R_ * H_ * 256,
                                               rel_msg + (size_t)l * R_ * H_ * 256, l);
        k_wsplit<<<WSPLIT_GRID, 256, 0, s_side>>>(Wq + woff, 1 + 4 * l);
        k_wsplit<<<WSPLIT_GRID, 256, 0, s_side>>>(Wk + woff, 2 + 4 * l);
        k_wsplit<<<WSPLIT_GRID, 256, 0, s_side>>>(Wv + woff, 3 + 4 * l);
        k_wsplit<<<WSPLIT_GRID, 256, 0, s_side>>>(Wa + woff, 4 + 4 * l);
    }
    k_init_layer<<<2048, 256, 0, s_side>>>();
    cudaEventRecord(evS, s_side);

    // ---- main: type buckets + adapt GEMM (overlaps side prep) ----
    k_build_type<<<(N_ + 255) / 256, 256>>>(node_type);
    k_wsplit<<<WSPLIT_GRID, 256>>>(adapt_w, 0);
    k_typed_gemm<<<ggrid, 256, GEMM_SMEM>>>(0, 1, node_feature, 0, adapt_b, px, px, nullptr);

    cudaStreamWaitEvent(0, evS, 0);   // join side prep

    for (int l = 0; l < 2; l++) {
        size_t boff = (size_t)l * T_ * 128;

        k_qkv_gemm<<<ggrid, 256, GEMM_SMEM>>>(px, 1 + 4 * l,
                                              bq + boff, bk + boff, bv + boff,
                                              pq, pk, pv);
        // side: transform Vn -> Vr (overlaps K-transform + edgeA/B)
        cudaEventRecord(evQ[l], 0);
        cudaStreamWaitEvent(s_side, evQ[l], 0);
        k_rel_gemm<<<rgrid, 256, REL_SMEM, s_side>>>(pv, pBDh + (size_t)(l * 2 + 1) * R_ * BDSZ_,
                                                     pBDl + (size_t)(l * 2 + 1) * R_ * BDSZ_, pVr);
        cudaEventRecord(evV[l], s_side);

        // main: Kn -> Kr
        k_rel_gemm<<<rgrid, 256, REL_SMEM>>>(pk, pBDh + (size_t)(l * 2 + 0) * R_ * BDSZ_,
                                             pBDl + (size_t)(l * 2 + 0) * R_ * BDSZ_, pKr);

        if (l == 1) cudaStreamWaitEvent(0, evU, 0);   // init_layer(l1) done

        k_edgeA<<<egrid, 256>>>(ptK0 + (size_t)l * TABSTRIDE,
                                rel_pri + (size_t)l * T_ * R_ * T_ * H_);
        k_edgeB<<<(E_ * H_ + 255) / 256, 256>>>();
        cudaStreamWaitEvent(0, evV[l], 0);
        k_edgeC<<<egrid, 256>>>(ptV0 + (size_t)l * TABSTRIDE);

        // x = alpha * typed_linear(gelu(aggr); Wa) + (1-alpha) * x
        float* outp = (l == 1) ? (float*)d_out : px;
        k_typed_gemm<<<ggrid, 256, GEMM_SMEM>>>(1, 2, pa, 4 + 4 * l, ba + boff,
                                                outp, px, skip + (size_t)l * T_);

        if (l == 0) {
            cudaEventRecord(evT, 0);
            cudaStreamWaitEvent(s_side, evT, 0);
            k_init_layer<<<2048, 256, 0, s_side>>>();
            cudaEventRecord(evU, s_side);
        }
    }
}

// round 6
// speedup vs baseline: 1.4180x; 1.0017x over previous
#include <cuda_runtime.h>
#include <cuda_bf16.h>
#include <math.h>

#define N_ 100000
#define E_ 500000
#define D_ 128
#define T_ 3
#define R_ 4
#define H_ 8
#define ML_ 240
#define TD_ ((size_t)N_*(size_t)D_)
#define PAD_ 136                        // bf16 elems per smem row (272B stride)
#define GEMM_SMEM (4 * 128 * PAD_ * 2)  // Ahi, Alo, Whi, Wlo
#define REL_SMEM  (2 * 128 * PAD_ * 2)  // Ahi, Alo only
#define NMAT_ 9                         // adapt + (q,k,v,a) x 2 layers
#define BDPAD_ 24
#define BDSZ_ (H_*16*BDPAD_)            // 3072 bf16 per (l,w,r) matrix
#define NPB_ ((N_ + 127) / 128)         // 782 target blocks
#define NB_  (R_ * NPB_)                // 3128 buckets

__device__ float g_x[TD_];
__device__ float g_Qn[TD_];
__device__ float g_Kn[TD_];
__device__ float g_Vn[TD_];
__device__ float g_aggr[TD_];
__device__ float g_Kr[(size_t)R_*N_*D_];
__device__ float g_Vr[(size_t)R_*N_*D_];
__device__ float g_score[(size_t)E_*H_];
__device__ float g_den[N_*H_];
__device__ float g_rte_tab[ML_*2*D_];
__device__ float g_rte_proj[ML_*D_];
__device__ float g_tabKr[2][(size_t)R_*T_*ML_*D_];
__device__ float g_tabVr[2][(size_t)R_*T_*ML_*D_];
__device__ __nv_bfloat16 g_Wh[(size_t)NMAT_*T_*D_*D_];
__device__ __nv_bfloat16 g_Wl[(size_t)NMAT_*T_*D_*D_];
__device__ __nv_bfloat16 g_BDh[2*2*R_*BDSZ_];
__device__ __nv_bfloat16 g_BDl[2*2*R_*BDSZ_];
__device__ int   g_typeList[T_][N_];
__device__ int   g_typeCnt[T_];
__device__ int   g_bCnt[NB_];
__device__ int   g_bOff[NB_+1];
__device__ int   g_bFill[NB_];
__device__ int   g_eS[E_];
__device__ int   g_eT[E_];
__device__ int   g_eMeta[E_];   // st | tt<<2 | time<<4

__device__ __forceinline__ float gelu_f(float x) { return x * normcdff(x); }

__device__ __forceinline__ void red_add_v4(float* p, float a, float b, float c, float d) {
    asm volatile("red.global.add.v4.f32 [%0], {%1,%2,%3,%4};"
                 :: "l"(p), "f"(a), "f"(b), "f"(c), "f"(d) : "memory");
}

// ---------------- mma helpers ----------------
__device__ __forceinline__ void ldsm4(unsigned& r0, unsigned& r1, unsigned& r2, unsigned& r3,
                                      unsigned addr) {
    asm volatile("ldmatrix.sync.aligned.m8n8.x4.shared.b16 {%0,%1,%2,%3}, [%4];"
                 : "=r"(r0), "=r"(r1), "=r"(r2), "=r"(r3) : "r"(addr));
}
__device__ __forceinline__ void ldsm4t(unsigned& r0, unsigned& r1, unsigned& r2, unsigned& r3,
                                       unsigned addr) {
    asm volatile("ldmatrix.sync.aligned.m8n8.x4.trans.shared.b16 {%0,%1,%2,%3}, [%4];"
                 : "=r"(r0), "=r"(r1), "=r"(r2), "=r"(r3) : "r"(addr));
}
__device__ __forceinline__ void mma16816(float* d, const unsigned* a, const unsigned* b) {
    asm volatile("mma.sync.aligned.m16n8k16.row.col.f32.bf16.bf16.f32 "
                 "{%0,%1,%2,%3}, {%4,%5,%6,%7}, {%8,%9}, {%0,%1,%2,%3};"
                 : "+f"(d[0]), "+f"(d[1]), "+f"(d[2]), "+f"(d[3])
                 : "r"(a[0]), "r"(a[1]), "r"(a[2]), "r"(a[3]), "r"(b[0]), "r"(b[1]));
}
__device__ __forceinline__ unsigned pack_bf2(__nv_bfloat16 a, __nv_bfloat16 b) {
    __nv_bfloat162 p(a, b);
    return *reinterpret_cast<unsigned*>(&p);
}

// ---------------- precompute kernels ----------------
__global__ void k_rte_tab() {
    int pos = blockIdx.x;
    int i   = threadIdx.x;
    const float s = 0.08838834764831845f;
    float div;
    if (i >= 5) div = 0.f;   // fp32 10000^ar overflow -> inf -> 0
    else {
        float pf = (float)pow(10000.0, (double)(2 * i));
        div = 1.0f / ((pf / 128.0f) / 2.0f);
    }
    float ang = (float)pos * div;
    double a = (double)ang;
    g_rte_tab[pos * 256 + 2 * i]     = (float)sin(a) * s;
    g_rte_tab[pos * 256 + 2 * i + 1] = (float)cos(a) * s;
}

__global__ void k_rte_proj(const float* __restrict__ w, const float* __restrict__ b) {
    int time = blockIdx.x;
    int d    = threadIdx.x;
    float acc = b[d];
    const float* tr = g_rte_tab + time * 256;
    for (int c = 0; c < 256; c++) acc += tr[c] * w[c * 128 + d];
    g_rte_proj[time * 128 + d] = acc;
}

__global__ void k_tables(const float* __restrict__ Wk, const float* __restrict__ Wv,
                         const float* __restrict__ relAtt, const float* __restrict__ relMsg,
                         int l) {
    __shared__ float sK[128], sV[128];
    int id = blockIdx.x;
    int d  = threadIdx.x;
    int t = id / ML_, time = id % ML_;
    const float* pr = g_rte_proj + time * 128;
    const float* wk = Wk + (size_t)t * 128 * 128;
    const float* wv = Wv + (size_t)t * 128 * 128;
    float aK = 0.f, aV = 0.f;
    for (int k = 0; k < 128; k++) {
        float p = pr[k];
        aK += p * wk[k * 128 + d];
        aV += p * wv[k * 128 + d];
    }
    sK[d] = aK; sV[d] = aV;
    __syncthreads();
    int h = d >> 4, dk = d & 15;
    size_t rowoff = (size_t)(t * ML_ + time) * 128 + d;
    for (int r = 0; r < R_; r++) {
        const float* A = relAtt + ((size_t)r * H_ + h) * 256;
        const float* M = relMsg + ((size_t)r * H_ + h) * 256;
        float k2 = 0.f, v2 = 0.f;
        #pragma unroll
        for (int j = 0; j < 16; j++) {
            k2 += sK[h * 16 + j] * A[j * 16 + dk];
            v2 += sV[h * 16 + j] * M[j * 16 + dk];
        }
        g_tabKr[l][(size_t)r * T_ * ML_ * D_ + rowoff] = k2;
        g_tabVr[l][(size_t)r * T_ * ML_ * D_ + rowoff] = v2;
    }
}

__global__ void k_wsplit(const float* __restrict__ src, int midx) {
    int i = blockIdx.x * blockDim.x + threadIdx.x;
    int n = T_ * D_ * D_;
    if (i >= n) return;
    size_t off = (size_t)midx * n + i;
    float v = src[i];
    __nv_bfloat16 h = __float2bfloat16_rn(v);
    g_Wh[off] = h;
    g_Wl[off] = __float2bfloat16_rn(v - __bfloat162float(h));
}

__global__ void k_relsplit(const float* __restrict__ relAtt, const float* __restrict__ relMsg) {
    int idx = blockIdx.x * blockDim.x + threadIdx.x;
    if (idx >= 2 * 2 * R_ * H_ * 256) return;
    int c = idx & 15, k = (idx >> 4) & 15, h = (idx >> 8) & 7;
    int r = (idx >> 11) & 3, w = (idx >> 13) & 1, l = idx >> 14;
    const float* src = w ? relMsg : relAtt;
    float v = src[(((size_t)l * R_ + r) * H_ + h) * 256 + k * 16 + c];
    __nv_bfloat16 hi = __float2bfloat16_rn(v);
    size_t dst = (size_t)(((l * 2 + w) * R_ + r)) * BDSZ_ + (h * 16 + k) * BDPAD_ + c;
    g_BDh[dst] = hi;
    g_BDl[dst] = __float2bfloat16_rn(v - __bfloat162float(hi));
}

// ---------------- bucketing: (relation, target-block) counting sort ----------------
__global__ void k_init_once() {
    int i = blockIdx.x * blockDim.x + threadIdx.x;
    if (i < NB_) { g_bCnt[i] = 0; g_bFill[i] = 0; }
    if (i < T_) g_typeCnt[i] = 0;
}

__global__ void k_build_type(const int* __restrict__ nt) {
    __shared__ int c[T_];
    __shared__ int base[T_];
    int tid = threadIdx.x;
    if (tid < T_) c[tid] = 0;
    __syncthreads();
    int i = blockIdx.x * blockDim.x + tid;
    int t = -1, rank = 0;
    if (i < N_) { t = nt[i]; rank = atomicAdd(&c[t], 1); }
    __syncthreads();
    if (tid < T_) base[tid] = c[tid] ? atomicAdd(&g_typeCnt[tid], c[tid]) : 0;
    __syncthreads();
    if (i < N_) g_typeList[t][base[t] + rank] = i;
}

__global__ void k_count_b(const int* __restrict__ tgt, const int* __restrict__ et) {
    int i = blockIdx.x * blockDim.x + threadIdx.x;
    if (i < E_) atomicAdd(&g_bCnt[et[i] * NPB_ + (tgt[i] >> 7)], 1);
}

// exclusive scan of g_bCnt[NB_] -> g_bOff (single block, 1024 threads)
__global__ void __launch_bounds__(1024) k_scan_b() {
    __shared__ int wsum[32];
    int tid = threadIdx.x;
    int v[4], s = 0;
    #pragma unroll
    for (int i = 0; i < 4; i++) {
        int idx = tid * 4 + i;
        v[i] = (idx < NB_) ? g_bCnt[idx] : 0;
        s += v[i];
    }
    int lane = tid & 31, w = tid >> 5;
    int incl = s;
    #pragma unroll
    for (int d = 1; d < 32; d <<= 1) {
        int o = __shfl_up_sync(0xffffffffu, incl, d);
        if (lane >= d) incl += o;
    }
    if (lane == 31) wsum[w] = incl;
    __syncthreads();
    if (w == 0) {
        int x = (lane < 32) ? wsum[lane] : 0;
        int in2 = x;
        #pragma unroll
        for (int d = 1; d < 32; d <<= 1) {
            int o = __shfl_up_sync(0xffffffffu, in2, d);
            if (lane >= d) in2 += o;
        }
        wsum[lane] = in2 - x;   // exclusive warp base
    }
    __syncthreads();
    int excl = wsum[w] + incl - s;
    #pragma unroll
    for (int i = 0; i < 4; i++) {
        int idx = tid * 4 + i;
        if (idx < NB_) g_bOff[idx] = excl;
        excl += v[i];
    }
    if (tid == 1023) g_bOff[NB_] = E_;
}

__global__ void k_scatter_b(const int* __restrict__ src, const int* __restrict__ tgt,
                            const int* __restrict__ et, const int* __restrict__ etm,
                            const int* __restrict__ nt) {
    int e = blockIdx.x * blockDim.x + threadIdx.x;
    if (e < E_) {
        int t = tgt[e];
        int key = et[e] * NPB_ + (t >> 7);
        int p = g_bOff[key] + atomicAdd(&g_bFill[key], 1);
        int s = src[e];
        g_eS[p] = s;
        g_eT[p] = t;
        g_eMeta[p] = nt[s] | (nt[t] << 2) | (etm[e] << 4);
    }
}

__global__ void k_init_layer() {
    int stride = gridDim.x * blockDim.x;
    int i0 = blockIdx.x * blockDim.x + threadIdx.x;
    for (int i = i0; i < N_ * H_; i += stride) g_den[i] = 0.f;
    for (size_t i = i0; i < TD_; i += (size_t)stride) g_aggr[i] = 0.f;
}

// ---------------- GEMM building blocks ----------------
__device__ __forceinline__ void load_w_smem(__nv_bfloat16* sWh, __nv_bfloat16* sWl,
                                            int midx, int t, int tid) {
    size_t base = ((size_t)midx * T_ + t) * D_ * D_;
    const uint4* wh4 = (const uint4*)(g_Wh + base);
    const uint4* wl4 = (const uint4*)(g_Wl + base);
    #pragma unroll
    for (int it = 0; it < 8; it++) {
        int idx = it * 256 + tid;
        int row = idx >> 4;
        int col = (idx & 15) * 8;
        *(uint4*)(sWh + row * PAD_ + col) = wh4[idx];
        *(uint4*)(sWl + row * PAD_ + col) = wl4[idx];
    }
}

__device__ __forceinline__ void cvt_store(__nv_bfloat16* sAh, __nv_bfloat16* sAl,
                                          int row, int col, float4 v) {
    __nv_bfloat16 h0 = __float2bfloat16_rn(v.x), h1 = __float2bfloat16_rn(v.y);
    __nv_bfloat16 h2 = __float2bfloat16_rn(v.z), h3 = __float2bfloat16_rn(v.w);
    __nv_bfloat16 l0 = __float2bfloat16_rn(v.x - __bfloat162float(h0));
    __nv_bfloat16 l1 = __float2bfloat16_rn(v.y - __bfloat162float(h1));
    __nv_bfloat16 l2 = __float2bfloat16_rn(v.z - __bfloat162float(h2));
    __nv_bfloat16 l3 = __float2bfloat16_rn(v.w - __bfloat162float(h3));
    *(uint2*)(sAh + row * PAD_ + col) = make_uint2(pack_bf2(h0, h1), pack_bf2(h2, h3));
    *(uint2*)(sAl + row * PAD_ + col) = make_uint2(pack_bf2(l0, l1), pack_bf2(l2, l3));
}

__device__ __forceinline__ void load_a_smem(__nv_bfloat16* sAh, __nv_bfloat16* sAl,
                                            const float* __restrict__ in,
                                            const int* sList, int inop, int tid) {
    #pragma unroll
    for (int it = 0; it < 16; it++) {
        int idx = it * 256 + tid;
        int row = idx >> 5;
        int col = (idx & 31) << 2;
        int grow = sList[row];
        float4 v = *(const float4*)(in + (size_t)grow * D_ + col);
        if (inop == 1) {
            v.x = gelu_f(v.x); v.y = gelu_f(v.y); v.z = gelu_f(v.z); v.w = gelu_f(v.w);
        }
        cvt_store(sAh, sAl, row, col, v);
    }
}

__device__ __forceinline__ void mma_tile(float (&acc)[2][8][4],
                                         const __nv_bfloat16* sAh, const __nv_bfloat16* sAl,
                                         const __nv_bfloat16* sWh, const __nv_bfloat16* sWl,
                                         int mbase, int nbase, int lane) {
    int aRow = mbase + (lane & 15);
    int aColAdd = (lane >> 4) << 3;
    int bg = lane >> 3;
    int bRowAdd = ((bg & 1) << 3) + (lane & 7);
    int bColAdd = (bg >> 1) << 3;

    unsigned aHbase = (unsigned)__cvta_generic_to_shared(sAh + aRow * PAD_);
    unsigned aLbase = (unsigned)__cvta_generic_to_shared(sAl + aRow * PAD_);
    unsigned wHbase = (unsigned)__cvta_generic_to_shared(sWh);
    unsigned wLbase = (unsigned)__cvta_generic_to_shared(sWl);

    #pragma unroll
    for (int kc = 0; kc < 8; kc++) {
        int k0 = kc * 16;
        unsigned ah[2][4], al[2][4];
        #pragma unroll
        for (int mt = 0; mt < 2; mt++) {
            unsigned off = (mt * 16 * PAD_ + k0 + aColAdd) * 2;
            ldsm4(ah[mt][0], ah[mt][1], ah[mt][2], ah[mt][3], aHbase + off);
            ldsm4(al[mt][0], al[mt][1], al[mt][2], al[mt][3], aLbase + off);
        }
        #pragma unroll
        for (int nt2 = 0; nt2 < 4; nt2++) {
            int nb = nbase + nt2 * 16;
            unsigned off = ((k0 + bRowAdd) * PAD_ + nb + bColAdd) * 2;
            unsigned bh[4], bl[4];
            ldsm4t(bh[0], bh[1], bh[2], bh[3], wHbase + off);
            ldsm4t(bl[0], bl[1], bl[2], bl[3], wLbase + off);
            #pragma unroll
            for (int mt = 0; mt < 2; mt++) {
                mma16816(acc[mt][nt2 * 2],     ah[mt], bh);
                mma16816(acc[mt][nt2 * 2],     al[mt], bh);
                mma16816(acc[mt][nt2 * 2],     ah[mt], bl);
                mma16816(acc[mt][nt2 * 2 + 1], ah[mt], bh + 2);
                mma16816(acc[mt][nt2 * 2 + 1], al[mt], bh + 2);
                mma16816(acc[mt][nt2 * 2 + 1], ah[mt], bl + 2);
            }
        }
    }
}

__device__ __forceinline__ void epi_bias(float (&acc)[2][8][4], const float* Bt,
                                         float* out, const int* sList, int rem,
                                         int mbase, int nbase, int lane) {
    int rq = lane >> 2, cq = (lane & 3) * 2;
    #pragma unroll
    for (int mt = 0; mt < 2; mt++) {
        int rl0 = mbase + mt * 16 + rq;
        #pragma unroll
        for (int nt = 0; nt < 8; nt++) {
            int col = nbase + nt * 8 + cq;
            float b0 = Bt[col], b1 = Bt[col + 1];
            float* a = acc[mt][nt];
            #pragma unroll
            for (int half = 0; half < 2; half++) {
                int rl = rl0 + half * 8;
                if (rl < rem) {
                    int grow = sList[rl];
                    float* op = out + (size_t)grow * D_ + col;
                    *(float2*)op = make_float2(a[half * 2] + b0, a[half * 2 + 1] + b1);
                }
            }
        }
    }
}

// ---------------- fused QKV GEMM ----------------
__global__ void __launch_bounds__(256) k_qkv_gemm(
    const float* __restrict__ in, int midx0,
    const float* __restrict__ Bq, const float* __restrict__ Bk, const float* __restrict__ Bv,
    float* __restrict__ Oq, float* __restrict__ Ok, float* __restrict__ Ov)
{
    int t = blockIdx.y;
    int cnt = g_typeCnt[t];
    int base = blockIdx.x * 128;
    if (base >= cnt) return;
    const int* list = &g_typeList[t][base];
    int rem = cnt - base; if (rem > 128) rem = 128;

    extern __shared__ __nv_bfloat16 sm[];
    __nv_bfloat16* sAh = sm;
    __nv_bfloat16* sAl = sAh + 128 * PAD_;
    __nv_bfloat16* sWh = sAl + 128 * PAD_;
    __nv_bfloat16* sWl = sWh + 128 * PAD_;
    __shared__ int sList[128];

    int tid = threadIdx.x;
    if (tid < 128) sList[tid] = (tid < rem) ? list[tid] : list[0];
    __syncthreads();

    load_a_smem(sAh, sAl, in, sList, 0, tid);

    int warp = tid >> 5, lane = tid & 31;
    int mbase = (warp & 3) * 32;
    int nbase = (warp >> 2) * 64;

    #pragma unroll
    for (int s = 0; s < 3; s++) {
        if (s > 0) __syncthreads();
        load_w_smem(sWh, sWl, midx0 + s, t, tid);
        __syncthreads();

        float acc[2][8][4];
        #pragma unroll
        for (int i = 0; i < 2; i++)
            #pragma unroll
            for (int j = 0; j < 8; j++)
                #pragma unroll
                for (int q = 0; q < 4; q++) acc[i][j][q] = 0.f;

        mma_tile(acc, sAh, sAl, sWh, sWl, mbase, nbase, lane);

        const float* Bt = (s == 0 ? Bq : s == 1 ? Bk : Bv) + t * D_;
        float* out = (s == 0 ? Oq : s == 1 ? Ok : Ov);
        epi_bias(acc, Bt, out, sList, rem, mbase, nbase, lane);
    }
}

// ---------------- single typed GEMM (adapt / trans) ----------------
__global__ void __launch_bounds__(256) k_typed_gemm(
    int inop, int outop,
    const float* __restrict__ in, int midx,
    const float* __restrict__ Bbase,
    float* __restrict__ out,
    const float* __restrict__ prev,
    const float* __restrict__ skipv)
{
    int t = blockIdx.y;
    int cnt = g_typeCnt[t];
    int base = blockIdx.x * 128;
    if (base >= cnt) return;
    const int* list = &g_typeList[t][base];
    int rem = cnt - base; if (rem > 128) rem = 128;

    extern __shared__ __nv_bfloat16 sm[];
    __nv_bfloat16* sAh = sm;
    __nv_bfloat16* sAl = sAh + 128 * PAD_;
    __nv_bfloat16* sWh = sAl + 128 * PAD_;
    __nv_bfloat16* sWl = sWh + 128 * PAD_;
    __shared__ int sList[128];

    int tid = threadIdx.x;
    if (tid < 128) sList[tid] = (tid < rem) ? list[tid] : list[0];
    __syncthreads();

    load_a_smem(sAh, sAl, in, sList, inop, tid);
    load_w_smem(sWh, sWl, midx, t, tid);
    __syncthreads();

    int warp = tid >> 5, lane = tid & 31;
    int mbase = (warp & 3) * 32;
    int nbase = (warp >> 2) * 64;

    float acc[2][8][4];
    #pragma unroll
    for (int i = 0; i < 2; i++)
        #pragma unroll
        for (int j = 0; j < 8; j++)
            #pragma unroll
            for (int q = 0; q < 4; q++) acc[i][j][q] = 0.f;

    mma_tile(acc, sAh, sAl, sWh, sWl, mbase, nbase, lane);

    const float* Bt = Bbase + t * D_;
    float alpha = 0.f, beta = 0.f;
    if (outop == 2) { alpha = 1.f / (1.f + expf(-skipv[t])); beta = 1.f - alpha; }

    int rq = lane >> 2, cq = (lane & 3) * 2;
    #pragma unroll
    for (int mt = 0; mt < 2; mt++) {
        int rl0 = mbase + mt * 16 + rq;
        #pragma unroll
        for (int nt = 0; nt < 8; nt++) {
            int col = nbase + nt * 8 + cq;
            float b0 = Bt[col], b1 = Bt[col + 1];
            float* a = acc[mt][nt];
            #pragma unroll
            for (int half = 0; half < 2; half++) {
                int rl = rl0 + half * 8;
                if (rl < rem) {
                    int grow = sList[rl];
                    float v0 = a[half * 2]     + b0;
                    float v1 = a[half * 2 + 1] + b1;
                    if (outop == 1) { v0 = tanhf(v0); v1 = tanhf(v1); }
                    else {
                        const float* pp = prev + (size_t)grow * D_ + col;
                        float2 old = *(const float2*)pp;
                        v0 = alpha * v0 + beta * old.x;
                        v1 = alpha * v1 + beta * old.y;
                    }
                    *(float2*)(out + (size_t)grow * D_ + col) = make_float2(v0, v1);
                }
            }
        }
    }
}

// ---------------- block-diagonal relation GEMM ----------------
__global__ void __launch_bounds__(256) k_rel_gemm(
    const float* __restrict__ in,
    const __nv_bfloat16* __restrict__ BDh, const __nv_bfloat16* __restrict__ BDl,
    float* __restrict__ out)
{
    int r = blockIdx.y;
    int base = blockIdx.x * 128;
    int rem = N_ - base; if (rem > 128) rem = 128;

    extern __shared__ __nv_bfloat16 sm[];
    __nv_bfloat16* sAh = sm;
    __nv_bfloat16* sAl = sAh + 128 * PAD_;
    __shared__ __nv_bfloat16 sBh[BDSZ_], sBl[BDSZ_];

    int tid = threadIdx.x;
    {
        const uint4* srcH = (const uint4*)(BDh + (size_t)r * BDSZ_);
        const uint4* srcL = (const uint4*)(BDl + (size_t)r * BDSZ_);
        uint4* dh = (uint4*)sBh;
        uint4* dl = (uint4*)sBl;
        for (int i = tid; i < BDSZ_ / 8; i += 256) { dh[i] = srcH[i]; dl[i] = srcL[i]; }
    }
    #pragma unroll
    for (int it = 0; it < 16; it++) {
        int idx = it * 256 + tid;
        int row = idx >> 5;
        int col = (idx & 31) << 2;
        int grow = base + (row < rem ? row : 0);
        float4 v = *(const float4*)(in + (size_t)grow * D_ + col);
        cvt_store(sAh, sAl, row, col, v);
    }
    __syncthreads();

    int warp = tid >> 5, lane = tid & 31;
    int mbase = (warp & 3) * 32;
    int nbase = (warp >> 2) * 64;

    float acc[2][8][4];
    #pragma unroll
    for (int i = 0; i < 2; i++)
        #pragma unroll
        for (int j = 0; j < 8; j++)
            #pragma unroll
            for (int q = 0; q < 4; q++) acc[i][j][q] = 0.f;

    int aColAdd = (lane >> 4) << 3;
    int bg = lane >> 3;
    int bRowAdd = ((bg & 1) << 3) + (lane & 7);
    int bColAdd = (bg >> 1) << 3;
    unsigned aHbase = (unsigned)__cvta_generic_to_shared(sAh + (mbase + (lane & 15)) * PAD_);
    unsigned aLbase = (unsigned)__cvta_generic_to_shared(sAl + (mbase + (lane & 15)) * PAD_);
    unsigned bHbase = (unsigned)__cvta_generic_to_shared(sBh);
    unsigned bLbase = (unsigned)__cvta_generic_to_shared(sBl);

    #pragma unroll
    for (int nt2 = 0; nt2 < 4; nt2++) {
        int head = (nbase >> 4) + nt2;
        unsigned ah[2][4], al[2][4];
        #pragma unroll
        for (int mt = 0; mt < 2; mt++) {
            unsigned offA = (mt * 16 * PAD_ + head * 16 + aColAdd) * 2;
            ldsm4(ah[mt][0], ah[mt][1], ah[mt][2], ah[mt][3], aHbase + offA);
            ldsm4(al[mt][0], al[mt][1], al[mt][2], al[mt][3], aLbase + offA);
        }
        unsigned offB = ((head * 16 + bRowAdd) * BDPAD_ + bColAdd) * 2;
        unsigned bh[4], bl[4];
        ldsm4t(bh[0], bh[1], bh[2], bh[3], bHbase + offB);
        ldsm4t(bl[0], bl[1], bl[2], bl[3], bLbase + offB);
        #pragma unroll
        for (int mt = 0; mt < 2; mt++) {
            mma16816(acc[mt][nt2 * 2],     ah[mt], bh);
            mma16816(acc[mt][nt2 * 2],     al[mt], bh);
            mma16816(acc[mt][nt2 * 2],     ah[mt], bl);
            mma16816(acc[mt][nt2 * 2 + 1], ah[mt], bh + 2);
            mma16816(acc[mt][nt2 * 2 + 1], al[mt], bh + 2);
            mma16816(acc[mt][nt2 * 2 + 1], ah[mt], bl + 2);
        }
    }

    float* outR = out + (size_t)r * N_ * D_;
    int rq = lane >> 2, cq = (lane & 3) * 2;
    #pragma unroll
    for (int mt = 0; mt < 2; mt++) {
        int rl0 = mbase + mt * 16 + rq;
        #pragma unroll
        for (int nt = 0; nt < 8; nt++) {
            int col = nbase + nt * 8 + cq;
            float* a = acc[mt][nt];
            #pragma unroll
            for (int half = 0; half < 2; half++) {
                int rl = rl0 + half * 8;
                if (rl < rem)
                    *(float2*)(outR + (size_t)(base + rl) * D_ + col) =
                        make_float2(a[half * 2], a[half * 2 + 1]);
            }
        }
    }
}

// ---------------- edge pass A: fused score + exp + segment sum ----------------
__global__ void __launch_bounds__(256) k_edgeA(const float* __restrict__ tabKr,
                                               const float* __restrict__ relPri) {
    int r = blockIdx.y;
    int lo = g_bOff[r * NPB_], hi = g_bOff[(r + 1) * NPB_];
    int lane = threadIdx.x & 31;
    int h = lane & 7, esub = lane >> 3;
    int warp = blockIdx.x * (blockDim.x >> 5) + (threadIdx.x >> 5);
    int nwarp = gridDim.x * (blockDim.x >> 5);
    const float* KrR = g_Kr + (size_t)r * N_ * D_;
    const float* tabR = tabKr + (size_t)r * T_ * ML_ * D_;

    for (int eb = lo + warp * 4; eb < hi; eb += nwarp * 4) {
        int p = eb + esub;
        bool valid = p < hi;
        if (!valid) p = lo;
        int s = g_eS[p], t = g_eT[p], meta = g_eMeta[p];
        int st = meta & 3, tt = (meta >> 2) & 3, tm = meta >> 4;

        const float4* kp = (const float4*)(KrR + (size_t)s * D_ + h * 16);
        const float4* tp = (const float4*)(tabR + (size_t)(st * ML_ + tm) * D_ + h * 16);
        const float4* qp = (const float4*)(g_Qn + (size_t)t * D_ + h * 16);
        float sc = 0.f;
        #pragma unroll
        for (int i = 0; i < 4; i++) {
            float4 k4 = kp[i], t4 = tp[i], q4 = qp[i];
            sc += q4.x * (k4.x + t4.x) + q4.y * (k4.y + t4.y)
                + q4.z * (k4.z + t4.z) + q4.w * (k4.w + t4.w);
        }
        float pri = relPri[((tt * R_ + r) * T_ + st) * H_ + h];
        // scores are O(1) (tanh-bounded inputs, 1/sqrt(D) weights): exp without
        // max-subtraction cannot overflow fp32; softmax is shift-invariant.
        float ex = expf(sc * pri * 0.25f);
        if (valid) {
            g_score[(size_t)p * H_ + h] = ex;
            atomicAdd(&g_den[t * H_ + h], ex);
        }
    }
}

// ---------------- edge pass C: weighted message scatter ----------------
__global__ void __launch_bounds__(256) k_edgeC(const float* __restrict__ tabVr) {
    int r = blockIdx.y;
    int lo = g_bOff[r * NPB_], hi = g_bOff[(r + 1) * NPB_];
    int lane = threadIdx.x & 31;
    int h = lane & 7, esub = lane >> 3;
    int warp = blockIdx.x * (blockDim.x >> 5) + (threadIdx.x >> 5);
    int nwarp = gridDim.x * (blockDim.x >> 5);
    const float* VrR = g_Vr + (size_t)r * N_ * D_;
    const float* tabR = tabVr + (size_t)r * T_ * ML_ * D_;

    for (int eb = lo + warp * 4; eb < hi; eb += nwarp * 4) {
        int p = eb + esub;
        bool valid = p < hi;
        if (!valid) p = lo;
        int s = g_eS[p], t = g_eT[p], meta = g_eMeta[p];
        int st = meta & 3, tm = meta >> 4;

        float ex = g_score[(size_t)p * H_ + h];
        float den = g_den[t * H_ + h];
        float att = ex / den;

        const float4* vp = (const float4*)(VrR + (size_t)s * D_ + h * 16);
        const float4* tp = (const float4*)(tabR + (size_t)(st * ML_ + tm) * D_ + h * 16);
        if (valid) {
            float* op = g_aggr + (size_t)t * D_ + h * 16;
            #pragma unroll
            for (int i = 0; i < 4; i++) {
                float4 v4 = vp[i], t4 = tp[i];
                red_add_v4(op + i * 4, (v4.x + t4.x) * att, (v4.y + t4.y) * att,
                                       (v4.z + t4.z) * att, (v4.w + t4.w) * att);
            }
        }
    }
}

// ---------------- launch ----------------
static cudaStream_t s_side = nullptr;
static cudaEvent_t evF = nullptr, evS = nullptr, evT = nullptr, evU = nullptr;
static cudaEvent_t evQ[2] = {nullptr, nullptr}, evV[2] = {nullptr, nullptr};

extern "C" void kernel_launch(void* const* d_in, const int* in_sizes, int n_in,
                              void* d_out, int out_size) {
    const float* node_feature = (const float*)d_in[0];
    const int*   node_type    = (const int*)d_in[1];
    const int*   edge_index   = (const int*)d_in[2];
    const int*   edge_type    = (const int*)d_in[3];
    const int*   edge_time    = (const int*)d_in[4];
    const float* adapt_w      = (const float*)d_in[5];
    const float* adapt_b      = (const float*)d_in[6];
    const float* Wk           = (const float*)d_in[7];
    const float* bk           = (const float*)d_in[8];
    const float* Wq           = (const float*)d_in[9];
    const float* bq           = (const float*)d_in[10];
    const float* Wv           = (const float*)d_in[11];
    const float* bv           = (const float*)d_in[12];
    const float* Wa           = (const float*)d_in[13];
    const float* ba           = (const float*)d_in[14];
    const float* rel_pri      = (const float*)d_in[15];
    const float* rel_att      = (const float*)d_in[16];
    const float* rel_msg      = (const float*)d_in[17];
    const float* skip         = (const float*)d_in[18];
    const float* rte_w        = (const float*)d_in[19];
    const float* rte_b        = (const float*)d_in[20];

    const int* src = edge_index;
    const int* tgt = edge_index + E_;

    if (!s_side) {
        cudaStreamCreateWithFlags(&s_side, cudaStreamNonBlocking);
        cudaEventCreateWithFlags(&evF, cudaEventDisableTiming);
        cudaEventCreateWithFlags(&evS, cudaEventDisableTiming);
        cudaEventCreateWithFlags(&evT, cudaEventDisableTiming);
        cudaEventCreateWithFlags(&evU, cudaEventDisableTiming);
        for (int i = 0; i < 2; i++) {
            cudaEventCreateWithFlags(&evQ[i], cudaEventDisableTiming);
            cudaEventCreateWithFlags(&evV[i], cudaEventDisableTiming);
        }
        cudaFuncSetAttribute(k_typed_gemm, cudaFuncAttributeMaxDynamicSharedMemorySize, GEMM_SMEM);
        cudaFuncSetAttribute(k_qkv_gemm, cudaFuncAttributeMaxDynamicSharedMemorySize, GEMM_SMEM);
        cudaFuncSetAttribute(k_rel_gemm, cudaFuncAttributeMaxDynamicSharedMemorySize, REL_SMEM);
    }

    float *px, *pq, *pk, *pv, *pa, *pKr, *pVr, *ptK0, *ptV0;
    __nv_bfloat16 *pBDh, *pBDl;
    cudaGetSymbolAddress((void**)&px, g_x);
    cudaGetSymbolAddress((void**)&pq, g_Qn);
    cudaGetSymbolAddress((void**)&pk, g_Kn);
    cudaGetSymbolAddress((void**)&pv, g_Vn);
    cudaGetSymbolAddress((void**)&pa, g_aggr);
    cudaGetSymbolAddress((void**)&pKr, g_Kr);
    cudaGetSymbolAddress((void**)&pVr, g_Vr);
    cudaGetSymbolAddress((void**)&ptK0, g_tabKr);
    cudaGetSymbolAddress((void**)&ptV0, g_tabVr);
    cudaGetSymbolAddress((void**)&pBDh, g_BDh);
    cudaGetSymbolAddress((void**)&pBDl, g_BDl);
    const size_t TABSTRIDE = (size_t)R_ * T_ * ML_ * D_;

    dim3 ggrid((N_ + 127) / 128, T_);
    dim3 rgrid((N_ + 127) / 128, R_);
    dim3 egrid(128, R_);
    const int WSPLIT_GRID = (T_ * D_ * D_ + 255) / 256;

    // ---- fork: side stream does all edge/table/weight prep ----
    cudaEventRecord(evF, 0);
    cudaStreamWaitEvent(s_side, evF, 0);

    k_init_once<<<(NB_ + 255) / 256, 256, 0, s_side>>>();
    k_count_b<<<(E_ + 255) / 256, 256, 0, s_side>>>(tgt, edge_type);
    k_scan_b<<<1, 1024, 0, s_side>>>();
    k_scatter_b<<<(E_ + 255) / 256, 256, 0, s_side>>>(src, tgt, edge_type, edge_time, node_type);
    k_rte_tab<<<ML_, 128, 0, s_side>>>();
    k_relsplit<<<(2 * 2 * R_ * H_ * 256 + 255) / 256, 256, 0, s_side>>>(rel_att, rel_msg);
    for (int l = 0; l < 2; l++) {
        size_t woff = (size_t)l * T_ * 128 * 128;
        k_rte_proj<<<ML_, 128, 0, s_side>>>(rte_w + (size_t)l * 256 * 128, rte_b + (size_t)l * 128);
        k_tables<<<T_ * ML_, 128, 0, s_side>>>(Wk + woff, Wv + woff,
                                               rel_att + (size_t)l * R_ * H_ * 256,
                                               rel_msg + (size_t)l * R_ * H_ * 256, l);
        k_wsplit<<<WSPLIT_GRID, 256, 0, s_side>>>(Wq + woff, 1 + 4 * l);
        k_wsplit<<<WSPLIT_GRID, 256, 0, s_side>>>(Wk + woff, 2 + 4 * l);
        k_wsplit<<<WSPLIT_GRID, 256, 0, s_side>>>(Wv + woff, 3 + 4 * l);
        k_wsplit<<<WSPLIT_GRID, 256, 0, s_side>>>(Wa + woff, 4 + 4 * l);
    }
    k_init_layer<<<2048, 256, 0, s_side>>>();
    cudaEventRecord(evS, s_side);

    // ---- main: type buckets + adapt GEMM (overlaps side prep) ----
    k_build_type<<<(N_ + 255) / 256, 256>>>(node_type);
    k_wsplit<<<WSPLIT_GRID, 256>>>(adapt_w, 0);
    k_typed_gemm<<<ggrid, 256, GEMM_SMEM>>>(0, 1, node_feature, 0, adapt_b, px, px, nullptr);

    cudaStreamWaitEvent(0, evS, 0);   // join side prep

    for (int l = 0; l < 2; l++) {
        size_t boff = (size_t)l * T_ * 128;

        k_qkv_gemm<<<ggrid, 256, GEMM_SMEM>>>(px, 1 + 4 * l,
                                              bq + boff, bk + boff, bv + boff,
                                              pq, pk, pv);
        // side: transform Vn -> Vr (overlaps K-transform + edgeA)
        cudaEventRecord(evQ[l], 0);
        cudaStreamWaitEvent(s_side, evQ[l], 0);
        k_rel_gemm<<<rgrid, 256, REL_SMEM, s_side>>>(pv, pBDh + (size_t)(l * 2 + 1) * R_ * BDSZ_,
                                                     pBDl + (size_t)(l * 2 + 1) * R_ * BDSZ_, pVr);
        cudaEventRecord(evV[l], s_side);

        // main: Kn -> Kr
        k_rel_gemm<<<rgrid, 256, REL_SMEM>>>(pk, pBDh + (size_t)(l * 2 + 0) * R_ * BDSZ_,
                                             pBDl + (size_t)(l * 2 + 0) * R_ * BDSZ_, pKr);

        if (l == 1) cudaStreamWaitEvent(0, evU, 0);   // init_layer(l1) done

        k_edgeA<<<egrid, 256>>>(ptK0 + (size_t)l * TABSTRIDE,
                                rel_pri + (size_t)l * T_ * R_ * T_ * H_);
        cudaStreamWaitEvent(0, evV[l], 0);
        k_edgeC<<<egrid, 256>>>(ptV0 + (size_t)l * TABSTRIDE);

        // x = alpha * typed_linear(gelu(aggr); Wa) + (1-alpha) * x
        float* outp = (l == 1) ? (float*)d_out : px;
        k_typed_gemm<<<ggrid, 256, GEMM_SMEM>>>(1, 2, pa, 4 + 4 * l, ba + boff,
                                                outp, px, skip + (size_t)l * T_);

        if (l == 0) {
            cudaEventRecord(evT, 0);
            cudaStreamWaitEvent(s_side, evT, 0);
            k_init_layer<<<2048, 256, 0, s_side>>>();
            cudaEventRecord(evU, s_side);
        }
    }
}